// round 11
// baseline (speedup 1.0000x reference)
#include <cuda_runtime.h>
#include <math.h>
#include <stdint.h>

// ---------------- problem constants ----------------
namespace {
constexpr int    Nv   = 4096;
constexpr int    Din  = 128;
constexpr int    Dh   = 256;
constexpr int    Kp   = 17;          // K+1
constexpr float  Eps  = 1e-8f;
constexpr float  InvT = 5.0f;        // 1/TEMP
constexpr size_t NN   = (size_t)Nv * (size_t)Nv;
constexpr int    Emax = 131072;
constexpr int    COO_CAP = 131072;
constexpr int    HCAP = 1 << 18;
constexpr int    CSR2_CAP = 160000;

// scratch heap layout (units: floats)
constexpr size_t O_SIM  = 0;
constexpr size_t O_X1   = O_SIM + NN;
constexpr size_t O_HN   = O_X1  + (size_t)Nv*Din;
constexpr size_t O_XW1  = O_HN  + (size_t)Nv*Dh;
constexpr size_t O_H1   = O_XW1 + (size_t)Nv*Dh;
constexpr size_t O_G1   = O_H1  + (size_t)Nv*Dh;
constexpr size_t O_BUFB = O_G1  + (size_t)Nv*Dh;
constexpr size_t O_BUFB2= O_BUFB+ (size_t)Nv*Dh;
constexpr size_t O_Z1   = O_BUFB2+(size_t)Nv*Dh;
constexpr size_t O_Z2   = O_Z1  + (size_t)Nv*Dh;
constexpr size_t O_W1T  = O_Z2  + (size_t)Nv*Dh;       // [Dh][Din]
constexpr size_t O_W2T  = O_W1T + (size_t)Dh*Din;      // [Dh][Dh]
constexpr size_t O_DEG  = O_W2T + (size_t)Dh*Dh;
constexpr size_t O_DINV = O_DEG + Nv;
constexpr size_t O_GS   = O_DINV+ Nv;
constexpr size_t O_PF   = O_GS  + Nv;
constexpr size_t O_PB   = O_PF  + Nv;
constexpr size_t O_GD   = O_PB  + Nv;
constexpr size_t O_RPTR = O_GD  + Nv;
constexpr size_t O_FILL = O_RPTR+ (Nv + 4);
constexpr size_t O_CSRC = O_FILL+ Nv;
constexpr size_t O_COOI = O_CSRC+ Emax;
constexpr size_t O_COOJ = O_COOI+ COO_CAP;
constexpr size_t O_COOW = O_COOJ+ COO_CAP;
constexpr size_t O_NNZ  = O_COOW+ COO_CAP;
constexpr size_t O_HKEY = O_NNZ + 4;
constexpr size_t O_HSUM = O_HKEY+ HCAP;
constexpr size_t O_HCNT = O_HSUM+ HCAP;
constexpr size_t O_DEG2 = O_HCNT+ HCAP;
constexpr size_t O_RPT2 = O_DEG2+ Nv;
constexpr size_t O_FIL2 = O_RPT2+ (Nv + 4);
constexpr size_t O_COL2 = O_FIL2+ Nv;
constexpr size_t O_WCS2 = O_COL2+ CSR2_CAP;
constexpr size_t TOTAL  = O_WCS2+ CSR2_CAP;

// GEMM smem: 2 stages x 2 arrays x 128 rows x 36 u32 (32 data + 4 pad)
constexpr unsigned SMEM_DYN = (2 * 2 * 4608 + 128) * 4;
}

__device__ __align__(256) float g_heap[TOTAL];

// ---------------- fast exp (FMA only) ----------------
__device__ __forceinline__ float fexp(float x) {
    float t  = x * 1.4426950408889634f;
    float rf = __fadd_rn(t, 12582912.0f);
    int   e  = __float_as_int(rf) - 0x4B400000;
    float r  = __fadd_rn(rf, -12582912.0f);
    float f  = t - r;
    float p  = fmaf(1.5403530394e-4f, f, 1.3333558146e-3f);
    p = fmaf(p, f, 9.6181291076e-3f);
    p = fmaf(p, f, 5.5504108665e-2f);
    p = fmaf(p, f, 2.4022650696e-1f);
    p = fmaf(p, f, 6.9314718056e-1f);
    p = fmaf(p, f, 1.0f);
    return __int_as_float(__float_as_int(p) + (e << 23));
}

// ---------------- tf32 helpers ----------------
__device__ __forceinline__ float tf32f(float x) {
    uint32_t r;
    asm("cvt.rna.tf32.f32 %0, %1;" : "=r"(r) : "f"(x));
    return __uint_as_float(r);
}
__device__ __forceinline__ void mma_tf32(float* c, const uint32_t* a, const uint32_t* b) {
    asm volatile(
        "mma.sync.aligned.m16n8k8.row.col.f32.tf32.tf32.f32 "
        "{%0,%1,%2,%3}, {%4,%5,%6,%7}, {%8,%9}, {%0,%1,%2,%3};"
        : "+f"(c[0]), "+f"(c[1]), "+f"(c[2]), "+f"(c[3])
        : "r"(a[0]), "r"(a[1]), "r"(a[2]), "r"(a[3]), "r"(b[0]), "r"(b[1]));
}
__device__ __forceinline__ uint32_t smem_u32(const void* p) {
    uint32_t a;
    asm("{ .reg .u64 t; cvta.to.shared.u64 t, %1; cvt.u32.u64 %0, t; }" : "=r"(a) : "l"(p));
    return a;
}
__device__ __forceinline__ void cpa16(uint32_t dst, const void* src) {
    asm volatile("cp.async.cg.shared.global [%0], [%1], 16;" :: "r"(dst), "l"(src));
}
#define CP_COMMIT() asm volatile("cp.async.commit_group;" ::: "memory")
#define LDMX4(r0, r1, r2, r3, addr) \
    asm volatile("ldmatrix.sync.aligned.m8n8.x4.shared.b16 {%0,%1,%2,%3}, [%4];" \
        : "=r"(r0), "=r"(r1), "=r"(r2), "=r"(r3) : "r"(addr))

// ---------------- hash insert helper ----------------
__device__ __forceinline__ void hash_insert(int r, int c, float v,
                                            int* hkey, float* hsum, int* hcnt) {
    if (v != v) v = 0.f;                      // nan_to_num
    int i = min(r, c), j = max(r, c);
    int key = (i << 12) | j;
    uint32_t slot = ((uint32_t)key * 2654435761u) >> 14;
    slot &= (HCAP - 1);
    while (true) {
        int old = atomicCAS(&hkey[slot], -1, key);
        if (old == -1 || old == key) break;
        slot = (slot + 1) & (HCAP - 1);
    }
    atomicAdd(&hsum[slot], v);
    atomicAdd(&hcnt[slot], 1);
}

// ---------------- init / small kernels ----------------
__global__ void init_k(float* deg, int* hkey, float* hsum, int* hcnt,
                       int* deg2, int* nnz, float* gs3) {
    int i = blockIdx.x * blockDim.x + threadIdx.x;
    if (i < HCAP) { hkey[i] = -1; hsum[i] = 0.f; hcnt[i] = 0; }
    if (i < Nv) { deg[i] = 1.f; deg2[i] = 0; }
    if (i < Nv * 3) gs3[i] = 0.f;
    if (i == 0) nnz[0] = 0;
}
__global__ void deg_count_k(const int* dst, float* deg, int E) {
    int e = blockIdx.x * blockDim.x + threadIdx.x;
    if (e < E) atomicAdd(&deg[dst[e]], 1.f);
}

__global__ void x1_k(const float* x, const float* pf, const float* ps, float* x1) {
    int i = blockIdx.x * blockDim.x + threadIdx.x;
    if (i >= Nv * Din) return;
    int c = i % Din;
    float v = x[i] * pf[c];
    x1[i] = tf32f(fmaxf(v, 0.f) * ps[c]);
}

// both weight transposes in one launch: z=0 -> W1 [Din,Dh], z=1 -> W2 [Dh,Dh]
__global__ void transpose2_k(const float* __restrict__ W1, const float* __restrict__ W2,
                             float* __restrict__ w1t, float* __restrict__ w2t) {
    __shared__ float tile[32][33];
    int z = blockIdx.z;
    int R  = z ? Dh : Din;
    const float* A = z ? W2 : W1;
    float* AT = z ? w2t : w1t;
    if (!z && blockIdx.y >= Din / 32) return;
    int x = blockIdx.x * 32 + threadIdx.x;
    int y = blockIdx.y * 32 + threadIdx.y;
    tile[threadIdx.y][threadIdx.x] = A[(size_t)y * Dh + x];
    __syncthreads();
    int xo = blockIdx.y * 32 + threadIdx.x;
    int yo = blockIdx.x * 32 + threadIdx.y;
    AT[(size_t)yo * R + xo] = tf32f(tile[threadIdx.x][threadIdx.y]);
}

// ---------------- fast single-block scans (warp shuffle, 2 barriers) ----------------
// FLAVOR 0: deg float (count = deg-1), also emits dinv. FLAVOR 1: deg2 int.
template<int FLAVOR>
__global__ void scan_k(const float* degf, const int* degi, float* dinv,
                       int* rowptr, int* fill) {
    __shared__ int ws[32];
    int t = threadIdx.x;
    int lane = t & 31, w = t >> 5;
    int c[4]; int loc = 0;
    #pragma unroll
    for (int q = 0; q < 4; q++) {
        if (FLAVOR == 0) {
            float d = degf[t * 4 + q];
            dinv[t * 4 + q] = rsqrtf(d);
            c[q] = (int)d - 1;
        } else {
            c[q] = degi[t * 4 + q];
        }
        loc += c[q];
    }
    int v = loc;
    #pragma unroll
    for (int o = 1; o < 32; o <<= 1) {
        int u = __shfl_up_sync(0xffffffffu, v, o);
        if (lane >= o) v += u;
    }
    if (lane == 31) ws[w] = v;
    __syncthreads();
    if (w == 0) {
        int s = ws[lane];
        #pragma unroll
        for (int o = 1; o < 32; o <<= 1) {
            int u = __shfl_up_sync(0xffffffffu, s, o);
            if (lane >= o) s += u;
        }
        ws[lane] = s;
    }
    __syncthreads();
    int base = (w > 0 ? ws[w - 1] : 0) + v - loc;
    #pragma unroll
    for (int q = 0; q < 4; q++) {
        rowptr[t * 4 + q] = base; base += c[q];
        fill[t * 4 + q] = 0;
    }
    if (t == 1023) rowptr[Nv] = base;
}

__global__ void fill_k(const int* es, const int* ed, const int* rowptr,
                       int* fill, int* csrc, int E) {
    int e = blockIdx.x * blockDim.x + threadIdx.x;
    if (e >= E) return;
    int d = ed[e];
    int p = rowptr[d] + atomicAdd(&fill[d], 1);
    csrc[p] = es[e];
}

// ---------------- CSR gather propagate ----------------
// EPI 0: plain. EPI 3 (F=Din): fused hn epilogue (bias = p_balance[2*Din]).
template<int F, int EPI>
__global__ void prop_k(const float* __restrict__ X, const int* __restrict__ rowptr,
                       const int* __restrict__ csrc, const float* __restrict__ dinv,
                       const float* __restrict__ bias, float* __restrict__ out) {
    __shared__ int   sI[F];
    __shared__ float sW[F];
    __shared__ float red[F];
    int r = blockIdx.x, t = threadIdx.x;
    int beg = rowptr[r], end = rowptr[r + 1];
    float acc = 0.f;
    for (int base = beg; base < end; base += F) {
        int m = min(F, end - base);
        if (t < m) { int s = csrc[base + t]; sI[t] = s; sW[t] = dinv[s]; }
        __syncthreads();
        #pragma unroll 4
        for (int q = 0; q < m; q++) acc += sW[q] * X[(size_t)sI[q] * F + t];
        __syncthreads();
    }
    float dv = dinv[r];
    float xv = X[(size_t)r * F + t];
    float v = dv * dv * xv + dv * acc;
    if (EPI == 0) {
        out[(size_t)r * F + t] = v;
    } else {
        float v1 = xv * bias[t];
        float v2 = v * bias[F + t];
        red[t] = v1 * v1 + v2 * v2; __syncthreads();
        for (int s = F / 2; s > 0; s >>= 1) { if (t < s) red[t] += red[t + s]; __syncthreads(); }
        float inv = 1.f / (sqrtf(red[0]) + Eps);
        out[(size_t)r * (2 * F) + t]     = tf32f(v1 * inv);
        out[(size_t)r * (2 * F) + F + t] = tf32f(v2 * inv);
    }
}

// ---------------- dual propagate: view1 (CSR1, gcn-norm) + view2 (CSR2, weighted) ----------------
// EPI 1: relu+bias. EPI 2: elu+bias+norm. blocks [0,Nv) -> view1, [Nv,2Nv) -> view2.
template<int EPI>
__global__ void dual_k(const float* __restrict__ X1, const float* __restrict__ X2,
                       const int* __restrict__ rptr1, const int* __restrict__ csrc,
                       const float* __restrict__ dinv,
                       const int* __restrict__ rpt2, const int* __restrict__ col2,
                       const float* __restrict__ wcs2,
                       const float* __restrict__ bias,
                       float* __restrict__ out1, float* __restrict__ out2) {
    __shared__ int   sI[Dh];
    __shared__ float sW[Dh];
    __shared__ float red[Dh];
    int bz = blockIdx.x >> 12;
    int r = blockIdx.x & (Nv - 1);
    int t = threadIdx.x;
    const float* X = bz ? X2 : X1;
    float* out = bz ? out2 : out1;
    int beg = bz ? rpt2[r] : rptr1[r];
    int end = bz ? rpt2[r + 1] : rptr1[r + 1];
    float acc = 0.f;
    for (int base = beg; base < end; base += Dh) {
        int m = min(Dh, end - base);
        if (t < m) {
            if (bz == 0) { int s = csrc[base + t]; sI[t] = s; sW[t] = dinv[s]; }
            else         { sI[t] = col2[base + t]; sW[t] = wcs2[base + t]; }
        }
        __syncthreads();
        #pragma unroll 4
        for (int q = 0; q < m; q++) acc += sW[q] * X[(size_t)sI[q] * Dh + t];
        __syncthreads();
    }
    float v;
    if (bz == 0) {
        float dv = dinv[r];
        v = dv * dv * X[(size_t)r * Dh + t] + dv * acc + bias[t];
    } else {
        v = acc + bias[t];
    }
    if (EPI == 1) {
        out[(size_t)r * Dh + t] = tf32f(fmaxf(v, 0.f));
    } else {
        v = v > 0.f ? v : expm1f(v);
        red[t] = v * v; __syncthreads();
        for (int s = Dh / 2; s > 0; s >>= 1) { if (t < s) red[t] += red[t + s]; __syncthreads(); }
        out[(size_t)r * Dh + t] = tf32f(v / (sqrtf(red[0]) + Eps));
    }
}

// ---------------- NT GEMM: TF32 mma (pre-rounded inputs), cp.async double buffer ----------------
template<bool FUSE>
__global__ __launch_bounds__(256)
void mma_nt_k(const float* __restrict__ A, const float* __restrict__ A2,
              const float* __restrict__ B,
              float* C, float* C2, float* __restrict__ gs, float* __restrict__ gdiag,
              int Kk, int Nc, int sym) {
    extern __shared__ uint32_t dsm[];
    float* rowsum = (float*)(dsm + 2 * 2 * 4608);

    int bx = blockIdx.x, by = blockIdx.y;
    if (sym && by > bx) return;
    if (blockIdx.z == 1) { A = A2; C = C2; }
    int brow = by * 128, bcol = bx * 128;
    int tid = threadIdx.x;
    int lane = tid & 31, wid = tid >> 5;
    int g = lane >> 2, tg = lane & 3;
    int lrow = lane & 7, lhalf = (lane >> 3) & 1, lcol = lane >> 4;
    int wm = (wid >> 1) * 32, wn = (wid & 1) * 64;
    int nch = Kk >> 5;
    uint32_t smb = smem_u32(dsm);

    auto issue = [&](int st, int c) {
        #pragma unroll
        for (int l = 0; l < 8; l++) {
            int id = l * 256 + tid;
            int arr = id >> 10;
            int rem = id & 1023;
            int row = rem >> 3, seg = rem & 7;
            const float* gp = arr ? B : A;
            int rb = arr ? bcol : brow;
            const float* src = gp + (size_t)(rb + row) * Kk + c * 32 + seg * 4;
            uint32_t dst = smb + ((st * 2 + arr) * 4608 + row * 36 + seg * 4) * 4;
            cpa16(dst, src);
        }
        CP_COMMIT();
    };

    float acc[2][8][4];
    #pragma unroll
    for (int mt = 0; mt < 2; mt++)
        #pragma unroll
        for (int nt = 0; nt < 8; nt++)
            #pragma unroll
            for (int q = 0; q < 4; q++) acc[mt][nt][q] = 0.f;

    issue(0, 0);
    issue(1, 1);

    for (int c = 0; c < nch; c++) {
        if (c + 1 < nch) asm volatile("cp.async.wait_group 1;" ::: "memory");
        else             asm volatile("cp.async.wait_group 0;" ::: "memory");
        __syncthreads();
        int st = c & 1;
        uint32_t bA = smb + (st * 2 + 0) * 18432;
        uint32_t bB = smb + (st * 2 + 1) * 18432;
        #pragma unroll
        for (int k8 = 0; k8 < 4; k8++) {
            int cb = k8 * 8 + lcol * 4;
            uint32_t af[2][4];
            #pragma unroll
            for (int mt = 0; mt < 2; mt++) {
                uint32_t off = bA + ((wm + mt * 16 + lrow + lhalf * 8) * 36 + cb) * 4;
                LDMX4(af[mt][0], af[mt][1], af[mt][2], af[mt][3], off);
            }
            uint32_t bf[8][2];
            #pragma unroll
            for (int np = 0; np < 4; np++) {
                uint32_t off = bB + ((wn + np * 16 + lrow + lhalf * 8) * 36 + cb) * 4;
                uint32_t t0, t1, t2, t3;
                LDMX4(t0, t1, t2, t3, off);
                bf[np * 2][0]     = t0; bf[np * 2][1]     = t2;
                bf[np * 2 + 1][0] = t1; bf[np * 2 + 1][1] = t3;
            }
            #pragma unroll
            for (int mt = 0; mt < 2; mt++)
                #pragma unroll
                for (int nt = 0; nt < 8; nt++)
                    mma_tf32(acc[mt][nt], af[mt], bf[nt]);
        }
        __syncthreads();
        if (c + 2 < nch) issue(st, c + 2);
    }

    if (!FUSE) {
        #pragma unroll
        for (int mt = 0; mt < 2; mt++)
            #pragma unroll
            for (int nt = 0; nt < 8; nt++) {
                int r0 = brow + wm + mt * 16 + g;
                int c0 = bcol + wn + nt * 8 + 2 * tg;
                *(float2*)(C + (size_t)r0 * Nc + c0)       = make_float2(acc[mt][nt][0], acc[mt][nt][1]);
                *(float2*)(C + (size_t)(r0 + 8) * Nc + c0) = make_float2(acc[mt][nt][2], acc[mt][nt][3]);
            }
        if (sym && bx != by) {
            float (*Tb)[130] = (float(*)[130])dsm;
            #pragma unroll
            for (int h = 0; h < 2; h++) {
                __syncthreads();
                if ((wid & 1) == h) {
                    #pragma unroll
                    for (int mt = 0; mt < 2; mt++)
                        #pragma unroll
                        for (int nt = 0; nt < 8; nt++) {
                            int rr = wm + mt * 16 + g;
                            int cl = nt * 8 + 2 * tg;
                            Tb[cl][rr]         = acc[mt][nt][0];
                            Tb[cl + 1][rr]     = acc[mt][nt][1];
                            Tb[cl][rr + 8]     = acc[mt][nt][2];
                            Tb[cl + 1][rr + 8] = acc[mt][nt][3];
                        }
                }
                __syncthreads();
                #pragma unroll
                for (int it = 0; it < 8; it++) {
                    int idx = tid + it * 256;
                    int rloc = idx >> 5, q = idx & 31;
                    float4 v = make_float4(Tb[rloc][4 * q], Tb[rloc][4 * q + 1],
                                           Tb[rloc][4 * q + 2], Tb[rloc][4 * q + 3]);
                    *(float4*)(C + (size_t)(bcol + h * 64 + rloc) * Nc + brow + 4 * q) = v;
                }
            }
        }
    } else {
        if (tid < 128) rowsum[tid] = 0.f;
        __syncthreads();
        #pragma unroll
        for (int mt = 0; mt < 2; mt++) {
            int lr0 = wm + mt * 16 + g;
            int gr0 = brow + lr0;
            float rs0 = 0.f, rs1 = 0.f;
            #pragma unroll
            for (int nt = 0; nt < 8; nt++) {
                int gc = bcol + wn + nt * 8 + 2 * tg;
                float e0 = fexp(InvT * acc[mt][nt][0]);
                float e1 = fexp(InvT * acc[mt][nt][1]);
                float e2 = fexp(InvT * acc[mt][nt][2]);
                float e3 = fexp(InvT * acc[mt][nt][3]);
                rs0 += e0 + e1;
                rs1 += e2 + e3;
                if (gc == gr0)         gdiag[gr0] = e0;
                if (gc + 1 == gr0)     gdiag[gr0] = e1;
                if (gc == gr0 + 8)     gdiag[gr0 + 8] = e2;
                if (gc + 1 == gr0 + 8) gdiag[gr0 + 8] = e3;
            }
            rs0 += __shfl_xor_sync(0xffffffffu, rs0, 1);
            rs0 += __shfl_xor_sync(0xffffffffu, rs0, 2);
            rs1 += __shfl_xor_sync(0xffffffffu, rs1, 1);
            rs1 += __shfl_xor_sync(0xffffffffu, rs1, 2);
            if (tg == 0) {
                atomicAdd(&rowsum[lr0], rs0);
                atomicAdd(&rowsum[lr0 + 8], rs1);
            }
        }
        __syncthreads();
        if (tid < 128) atomicAdd(&gs[brow + tid], rowsum[tid]);
    }
}

// ---------------- top-k (cached local maxima) + fused hash insertion ----------------
__global__ void topk_k(const float* __restrict__ sim,
                       int* hkey, float* hsum, int* hcnt) {
    __shared__ float sv[Nv];
    __shared__ float lv[256];
    __shared__ int   li[256];
    __shared__ float wv[8];
    __shared__ int   wi[8];
    __shared__ float stv[Kp];
    __shared__ int   sti[Kp];
    int r = blockIdx.x, t = threadIdx.x;
    float best = -1e30f; int besti = 1 << 30;
    #pragma unroll
    for (int q = 0; q < 16; q++) {
        int i = t + q * 256;
        float v = sim[(size_t)r * Nv + i];
        sv[i] = v;
        if (v > best) { best = v; besti = i; }
    }
    lv[t] = best; li[t] = besti;
    __syncthreads();
    for (int k = 0; k < Kp; k++) {
        float b = lv[t]; int bi = li[t];
        #pragma unroll
        for (int o = 16; o > 0; o >>= 1) {
            float ov = __shfl_down_sync(0xffffffffu, b, o);
            int   oi = __shfl_down_sync(0xffffffffu, bi, o);
            if (ov > b || (ov == b && oi < bi)) { b = ov; bi = oi; }
        }
        if ((t & 31) == 0) { wv[t >> 5] = b; wi[t >> 5] = bi; }
        __syncthreads();
        if (t == 0) {
            float bb = wv[0]; int bj = wi[0];
            #pragma unroll
            for (int w = 1; w < 8; w++)
                if (wv[w] > bb || (wv[w] == bb && wi[w] < bj)) { bb = wv[w]; bj = wi[w]; }
            stv[k] = bb; sti[k] = bj;
            sv[bj] = -1e30f;
            wi[0] = bj;
        }
        __syncthreads();
        int bj = wi[0];
        if ((bj & 255) == t) {
            float nb = -1e30f; int ni = 1 << 30;
            #pragma unroll
            for (int q = 0; q < 16; q++) {
                int i = t + q * 256;
                float v = sv[i];
                if (v > nb) { nb = v; ni = i; }
            }
            lv[t] = nb; li[t] = ni;
        }
        __syncthreads();
    }
    if (t < Kp) hash_insert(r, sti[t], stv[t], hkey, hsum, hcnt);
}

// ---------------- hash emit -> COO + degrees ----------------
__global__ void hash_emit_k(const int* hkey, const float* hsum, const int* hcnt,
                            int* cooi, int* cooj, float* coow, int* nnz, int* deg2) {
    int s = blockIdx.x * blockDim.x + threadIdx.x;
    if (s >= HCAP) return;
    int key = hkey[s];
    if (key < 0) return;
    float o = hsum[s] / (float)hcnt[s];
    if (o <= 0.f) return;
    int i = key >> 12, j = key & 4095;
    int p = atomicAdd(nnz, 1);
    cooi[p] = i; cooj[p] = j; coow[p] = o;
    atomicAdd(&deg2[i], 1);
    if (i != j) atomicAdd(&deg2[j], 1);
}

__global__ void fill2_k(const int* cooi, const int* cooj, const float* coow,
                        const int* nnz, const int* rowptr, int* fill,
                        int* col2, float* w2) {
    int e = blockIdx.x * blockDim.x + threadIdx.x;
    if (e >= *nnz) return;
    int i = cooi[e], j = cooj[e];
    float o = coow[e];
    int p = rowptr[i] + atomicAdd(&fill[i], 1);
    col2[p] = j; w2[p] = o;
    if (i != j) {
        p = rowptr[j] + atomicAdd(&fill[j], 1);
        col2[p] = i; w2[p] = o;
    }
}

// ---------------- pf/pb over COO nonzeros ----------------
__global__ void pfpb_k(const int* coo_i, const int* coo_j, const float* coo_w,
                       const int* nnz, const float* __restrict__ z1,
                       const float* __restrict__ z2, const float* gs,
                       float* pf, float* pb) {
    int wid = (blockIdx.x * blockDim.x + threadIdx.x) >> 5;
    int lane = threadIdx.x & 31;
    if (wid >= *nnz) return;
    int i = coo_i[wid], j = coo_j[wid];
    float wt = coo_w[wid];
    float d1 = 0.f, d2 = 0.f;
    #pragma unroll
    for (int q = 0; q < 8; q++) {
        int c = lane + q * 32;
        d1 += z1[(size_t)i * Dh + c] * z2[(size_t)j * Dh + c];
    }
    if (i != j) {
        #pragma unroll
        for (int q = 0; q < 8; q++) {
            int c = lane + q * 32;
            d2 += z1[(size_t)j * Dh + c] * z2[(size_t)i * Dh + c];
        }
    }
    #pragma unroll
    for (int o = 16; o > 0; o >>= 1) {
        d1 += __shfl_xor_sync(0xffffffffu, d1, o);
        d2 += __shfl_xor_sync(0xffffffffu, d2, o);
    }
    if (lane == 0) {
        float q1 = fexp(InvT * d1) / gs[i] * wt;
        atomicAdd(&pf[i], q1);
        atomicAdd(&pb[j], q1);
        if (i != j) {
            float q2 = fexp(InvT * d2) / gs[j] * wt;
            atomicAdd(&pf[j], q2);
            atomicAdd(&pb[i], q2);
        }
    }
}

__global__ void loss_k(const float* gdiag, const float* gs,
                       const float* pf, const float* pb, float* out) {
    __shared__ float s1[256], s2[256], s3[256];
    int t = threadIdx.x;
    float a = 0.f, b = 0.f, c = 0.f;
    for (int i = t; i < Nv; i += 256) {
        a -= logf(fmaxf(gdiag[i] / gs[i], Eps));
        b -= logf(fmaxf(pf[i], Eps));
        c -= logf(fmaxf(pb[i], Eps));
    }
    s1[t] = a; s2[t] = b; s3[t] = c; __syncthreads();
    for (int st = 128; st > 0; st >>= 1) {
        if (t < st) { s1[t] += s1[t + st]; s2[t] += s2[t + st]; s3[t] += s3[t + st]; }
        __syncthreads();
    }
    if (t == 0) out[0] = s1[0] / Nv + 0.5f * (s2[0] / Nv + s3[0] / Nv);
}

// ---------------- host launcher ----------------
extern "C" void kernel_launch(void* const* d_in, const int* in_sizes, int n_in,
                              void* d_out, int out_size) {
    const float* x       = (const float*)d_in[0];
    const int*   esrc    = (const int*)d_in[1];
    const int*   edst    = (const int*)d_in[2];
    const float* p_feat  = (const float*)d_in[3];
    const float* p_share = (const float*)d_in[4];
    const float* p_bal   = (const float*)d_in[5];
    const float* W1      = (const float*)d_in[6];
    const float* b1      = (const float*)d_in[7];
    const float* W2      = (const float*)d_in[8];
    const float* b2      = (const float*)d_in[9];
    float* out = (float*)d_out;
    int E = in_sizes[1];

    float* H = nullptr;
    cudaGetSymbolAddress((void**)&H, g_heap);
    float* sim  = H + O_SIM;
    float* x1   = H + O_X1;   float* hn  = H + O_HN;
    float* xw1  = H + O_XW1;  float* h1   = H + O_H1;   float* g1  = H + O_G1;
    float* bufB = H + O_BUFB; float* bufB2 = H + O_BUFB2;
    float* z1   = H + O_Z1;   float* z2   = H + O_Z2;
    float* w1t  = H + O_W1T;  float* w2t  = H + O_W2T;
    float* deg  = H + O_DEG;  float* dinv = H + O_DINV;
    float* gs   = H + O_GS;   float* pf   = H + O_PF;   float* pb  = H + O_PB;
    float* gd   = H + O_GD;
    int*   rptr = (int*)(H + O_RPTR);
    int*   fill = (int*)(H + O_FILL);
    int*   csrc = (int*)(H + O_CSRC);
    int*   cooi = (int*)(H + O_COOI);
    int*   cooj = (int*)(H + O_COOJ);
    float* coow = H + O_COOW;
    int*   nnz  = (int*)(H + O_NNZ);
    int*   hkey = (int*)(H + O_HKEY);
    float* hsum = H + O_HSUM;
    int*   hcnt = (int*)(H + O_HCNT);
    int*   deg2 = (int*)(H + O_DEG2);
    int*   rpt2 = (int*)(H + O_RPT2);
    int*   fil2 = (int*)(H + O_FIL2);
    int*   col2 = (int*)(H + O_COL2);
    float* wcs2 = H + O_WCS2;

    cudaFuncSetAttribute(mma_nt_k<false>, cudaFuncAttributeMaxDynamicSharedMemorySize, SMEM_DYN);
    cudaFuncSetAttribute(mma_nt_k<true>,  cudaFuncAttributeMaxDynamicSharedMemorySize, SMEM_DYN);

    // prologue + CSR build
    x1_k<<<(Nv * Din) / 256, 256>>>(x, p_feat, p_share, x1);
    init_k<<<HCAP / 256, 256>>>(deg, hkey, hsum, hcnt, deg2, nnz, gs);
    deg_count_k<<<(E + 255) / 256, 256>>>(edst, deg, E);
    scan_k<0><<<1, 1024>>>(deg, nullptr, dinv, rptr, fill);
    fill_k<<<(E + 255) / 256, 256>>>(esrc, edst, rptr, fill, csrc, E);

    // propagate + fused hn
    prop_k<Din, 3><<<Nv, Din>>>(x1, rptr, csrc, dinv, p_bal, hn);

    // weights transpose (fused)
    transpose2_k<<<dim3(Dh / 32, Dh / 32, 2), dim3(32, 32)>>>(W1, W2, w1t, w2t);

    // xw1 = x1 @ W1
    mma_nt_k<false><<<dim3(2, 32, 1), 256, SMEM_DYN>>>(
        x1, nullptr, w1t, xw1, nullptr, nullptr, nullptr, Din, Dh, 0);

    // sim = hn @ hn^T (symmetric, tf32)
    mma_nt_k<false><<<dim3(32, 32, 1), 256, SMEM_DYN>>>(
        hn, nullptr, hn, sim, nullptr, nullptr, nullptr, Dh, Nv, 1);

    // top-k (fused hash insert) -> emit -> CSR2
    topk_k<<<Nv, 256>>>(sim, hkey, hsum, hcnt);
    hash_emit_k<<<HCAP / 256, 256>>>(hkey, hsum, hcnt, cooi, cooj, coow, nnz, deg2);
    scan_k<1><<<1, 1024>>>(nullptr, deg2, nullptr, rpt2, fil2);
    fill2_k<<<(Nv * Kp + 255) / 256, 256>>>(cooi, cooj, coow, nnz, rpt2, fil2, col2, wcs2);

    // layer 1 (both views, one launch), batched W2 GEMM, layer 2 (both views)
    dual_k<1><<<2 * Nv, Dh>>>(xw1, xw1, rptr, csrc, dinv, rpt2, col2, wcs2, b1, h1, g1);
    mma_nt_k<false><<<dim3(2, 32, 2), 256, SMEM_DYN>>>(
        h1, g1, w2t, bufB, bufB2, nullptr, nullptr, Dh, Dh, 0);
    dual_k<2><<<2 * Nv, Dh>>>(bufB, bufB2, rptr, csrc, dinv, rpt2, col2, wcs2, b2, z1, z2);

    // fused z1n @ z2n^T: row exp-sums + diag
    mma_nt_k<true><<<dim3(32, 32, 1), 256, SMEM_DYN>>>(
        z1, nullptr, z2, nullptr, nullptr, gs, gd, Dh, Nv, 0);

    // pf/pb + loss
    pfpb_k<<<COO_CAP / 8, 256>>>(cooi, cooj, coow, nnz, z1, z2, gs, pf, pb);
    loss_k<<<1, 256>>>(gd, gs, pf, pb, out);
}

// round 12
// speedup vs baseline: 1.5132x; 1.5132x over previous
#include <cuda_runtime.h>
#include <math.h>
#include <stdint.h>

// ---------------- problem constants ----------------
namespace {
constexpr int    Nv   = 4096;
constexpr int    Din  = 128;
constexpr int    Dh   = 256;
constexpr int    Kp   = 17;          // K+1
constexpr float  Eps  = 1e-8f;
constexpr float  InvT = 5.0f;        // 1/TEMP
constexpr size_t NN   = (size_t)Nv * (size_t)Nv;
constexpr int    Emax = 131072;
constexpr int    HCAP = 1 << 18;
constexpr int    CSR2_CAP = 160000;

// scratch heap layout (units: floats)
constexpr size_t O_SIM  = 0;
constexpr size_t O_X1   = O_SIM + NN;
constexpr size_t O_HN   = O_X1  + (size_t)Nv*Din;
constexpr size_t O_XW1  = O_HN  + (size_t)Nv*Dh;
constexpr size_t O_H1   = O_XW1 + (size_t)Nv*Dh;
constexpr size_t O_G1   = O_H1  + (size_t)Nv*Dh;
constexpr size_t O_BUFB = O_G1  + (size_t)Nv*Dh;
constexpr size_t O_BUFB2= O_BUFB+ (size_t)Nv*Dh;
constexpr size_t O_Z1   = O_BUFB2+(size_t)Nv*Dh;
constexpr size_t O_Z2   = O_Z1  + (size_t)Nv*Dh;
constexpr size_t O_W1T  = O_Z2  + (size_t)Nv*Dh;       // [Dh][Din]
constexpr size_t O_W2T  = O_W1T + (size_t)Dh*Din;      // [Dh][Dh]
constexpr size_t O_DEG  = O_W2T + (size_t)Dh*Dh;
constexpr size_t O_DINV = O_DEG + Nv;
constexpr size_t O_GS   = O_DINV+ Nv;
constexpr size_t O_PF   = O_GS  + Nv;
constexpr size_t O_PB   = O_PF  + Nv;
constexpr size_t O_GD   = O_PB  + Nv;
constexpr size_t O_RPTR = O_GD  + Nv;
constexpr size_t O_FILL = O_RPTR+ (Nv + 4);
constexpr size_t O_CSRC = O_FILL+ Nv;
constexpr size_t O_TOPI = O_CSRC+ Emax;
constexpr size_t O_TOPV = O_TOPI+ (size_t)Nv*Kp;
constexpr size_t O_COOI = O_TOPV+ (size_t)Nv*Kp;
constexpr size_t O_COOJ = O_COOI+ (size_t)Nv*Kp;
constexpr size_t O_COOW = O_COOJ+ (size_t)Nv*Kp;
constexpr size_t O_NNZ  = O_COOW+ (size_t)Nv*Kp;
constexpr size_t O_HKEY = O_NNZ + 4;
constexpr size_t O_HSUM = O_HKEY+ HCAP;
constexpr size_t O_HCNT = O_HSUM+ HCAP;
constexpr size_t O_DEG2 = O_HCNT+ HCAP;
constexpr size_t O_RPT2 = O_DEG2+ Nv;
constexpr size_t O_FIL2 = O_RPT2+ (Nv + 4);
constexpr size_t O_COL2 = O_FIL2+ Nv;
constexpr size_t O_WCS2 = O_COL2+ CSR2_CAP;
constexpr size_t TOTAL  = O_WCS2+ CSR2_CAP;

// GEMM smem: 2 stages x 2 arrays x 128 rows x 36 u32 (32 data + 4 pad)
constexpr unsigned SMEM_DYN = (2 * 2 * 4608 + 128) * 4;
}

__device__ __align__(256) float g_heap[TOTAL];

// ---------------- fast exp (FMA only) ----------------
__device__ __forceinline__ float fexp(float x) {
    float t  = x * 1.4426950408889634f;
    float rf = __fadd_rn(t, 12582912.0f);
    int   e  = __float_as_int(rf) - 0x4B400000;
    float r  = __fadd_rn(rf, -12582912.0f);
    float f  = t - r;
    float p  = fmaf(1.5403530394e-4f, f, 1.3333558146e-3f);
    p = fmaf(p, f, 9.6181291076e-3f);
    p = fmaf(p, f, 5.5504108665e-2f);
    p = fmaf(p, f, 2.4022650696e-1f);
    p = fmaf(p, f, 6.9314718056e-1f);
    p = fmaf(p, f, 1.0f);
    return __int_as_float(__float_as_int(p) + (e << 23));
}

// ---------------- tf32 helpers ----------------
__device__ __forceinline__ float tf32f(float x) {
    uint32_t r;
    asm("cvt.rna.tf32.f32 %0, %1;" : "=r"(r) : "f"(x));
    return __uint_as_float(r);
}
__device__ __forceinline__ void mma_tf32(float* c, const uint32_t* a, const uint32_t* b) {
    asm volatile(
        "mma.sync.aligned.m16n8k8.row.col.f32.tf32.tf32.f32 "
        "{%0,%1,%2,%3}, {%4,%5,%6,%7}, {%8,%9}, {%0,%1,%2,%3};"
        : "+f"(c[0]), "+f"(c[1]), "+f"(c[2]), "+f"(c[3])
        : "r"(a[0]), "r"(a[1]), "r"(a[2]), "r"(a[3]), "r"(b[0]), "r"(b[1]));
}
__device__ __forceinline__ uint32_t smem_u32(const void* p) {
    uint32_t a;
    asm("{ .reg .u64 t; cvta.to.shared.u64 t, %1; cvt.u32.u64 %0, t; }" : "=r"(a) : "l"(p));
    return a;
}
__device__ __forceinline__ void cpa16(uint32_t dst, const void* src) {
    asm volatile("cp.async.cg.shared.global [%0], [%1], 16;" :: "r"(dst), "l"(src));
}
#define CP_COMMIT() asm volatile("cp.async.commit_group;" ::: "memory")
#define LDMX4(r0, r1, r2, r3, addr) \
    asm volatile("ldmatrix.sync.aligned.m8n8.x4.shared.b16 {%0,%1,%2,%3}, [%4];" \
        : "=r"(r0), "=r"(r1), "=r"(r2), "=r"(r3) : "r"(addr))

// ---------------- init (fused with x1 compute) ----------------
__global__ void init_k(float* deg, int* hkey, float* hsum, int* hcnt,
                       int* deg2, int* nnz, float* gs3,
                       const float* __restrict__ x, const float* __restrict__ pf,
                       const float* __restrict__ ps, float* __restrict__ x1) {
    int i = blockIdx.x * blockDim.x + threadIdx.x;     // 0 .. Nv*Din-1 (524288)
    if (i < HCAP) { hkey[i] = -1; hsum[i] = 0.f; hcnt[i] = 0; }
    if (i < Nv) { deg[i] = 1.f; deg2[i] = 0; }
    if (i < Nv * 3) gs3[i] = 0.f;
    if (i == 0) nnz[0] = 0;
    int c = i % Din;
    float v = x[i] * pf[c];
    x1[i] = tf32f(fmaxf(v, 0.f) * ps[c]);
}

__global__ void deg_count_k(const int* dst, float* deg, int E) {
    int e = blockIdx.x * blockDim.x + threadIdx.x;
    if (e < E) atomicAdd(&deg[dst[e]], 1.f);
}

// both weight transposes in one launch: z=0 -> W1 [Din,Dh], z=1 -> W2 [Dh,Dh]
__global__ void transpose2_k(const float* __restrict__ W1, const float* __restrict__ W2,
                             float* __restrict__ w1t, float* __restrict__ w2t) {
    __shared__ float tile[32][33];
    int z = blockIdx.z;
    int R  = z ? Dh : Din;
    const float* A = z ? W2 : W1;
    float* AT = z ? w2t : w1t;
    if (!z && blockIdx.y >= Din / 32) return;
    int x = blockIdx.x * 32 + threadIdx.x;
    int y = blockIdx.y * 32 + threadIdx.y;
    tile[threadIdx.y][threadIdx.x] = A[(size_t)y * Dh + x];
    __syncthreads();
    int xo = blockIdx.y * 32 + threadIdx.x;
    int yo = blockIdx.x * 32 + threadIdx.y;
    AT[(size_t)yo * R + xo] = tf32f(tile[threadIdx.x][threadIdx.y]);
}

// ---------------- CSR build (original graph) ----------------
__global__ void scan_k(const float* deg, float* dinv, int* rowptr, int* fill) {
    __shared__ int s[1024];
    int t = threadIdx.x;
    int c[4]; int loc = 0;
    #pragma unroll
    for (int q = 0; q < 4; q++) {
        float d = deg[t * 4 + q];
        dinv[t * 4 + q] = rsqrtf(d);
        c[q] = (int)d - 1; loc += c[q];
    }
    s[t] = loc; __syncthreads();
    for (int off = 1; off < 1024; off <<= 1) {
        int v = (t >= off) ? s[t - off] : 0;
        __syncthreads();
        s[t] += v;
        __syncthreads();
    }
    int run = s[t] - loc;
    #pragma unroll
    for (int q = 0; q < 4; q++) {
        rowptr[t * 4 + q] = run; run += c[q];
        fill[t * 4 + q] = 0;
    }
    if (t == 1023) rowptr[Nv] = run;
}

__global__ void fill_k(const int* es, const int* ed, const int* rowptr,
                       int* fill, int* csrc, int E) {
    int e = blockIdx.x * blockDim.x + threadIdx.x;
    if (e >= E) return;
    int d = ed[e];
    int p = rowptr[d] + atomicAdd(&fill[d], 1);
    csrc[p] = es[e];
}

// ---------------- CSR gather propagate ----------------
// EPI 0: plain. EPI 1: relu+bias (tf32). EPI 2: elu+bias+norm (tf32).
// EPI 3 (F=Din): fused hn epilogue -> out is hn [Nv, Dh], bias is p_balance[2*Din].
template<int F, int EPI>
__global__ void prop_k(const float* __restrict__ X, const int* __restrict__ rowptr,
                       const int* __restrict__ csrc, const float* __restrict__ dinv,
                       const float* __restrict__ bias, float* __restrict__ out) {
    __shared__ int   sI[F];
    __shared__ float sW[F];
    __shared__ float red[(EPI >= 2) ? F : 1];
    int r = blockIdx.x, t = threadIdx.x;
    int beg = rowptr[r], end = rowptr[r + 1];
    float acc = 0.f;
    for (int base = beg; base < end; base += F) {
        int m = min(F, end - base);
        if (t < m) { int s = csrc[base + t]; sI[t] = s; sW[t] = dinv[s]; }
        __syncthreads();
        #pragma unroll 4
        for (int q = 0; q < m; q++) acc += sW[q] * X[(size_t)sI[q] * F + t];
        __syncthreads();
    }
    float dv = dinv[r];
    float xv = X[(size_t)r * F + t];
    float v = dv * dv * xv + dv * acc;
    if (EPI == 0) {
        out[(size_t)r * F + t] = v;
    } else if (EPI == 1) {
        out[(size_t)r * F + t] = tf32f(fmaxf(v + bias[t], 0.f));
    } else if (EPI == 2) {
        v += bias[t];
        v = v > 0.f ? v : expm1f(v);
        red[t] = v * v; __syncthreads();
        for (int s = F / 2; s > 0; s >>= 1) { if (t < s) red[t] += red[t + s]; __syncthreads(); }
        out[(size_t)r * F + t] = tf32f(v / (sqrtf(red[0]) + Eps));
    } else {
        // fused hn: h = [x1, agg] * p_balance, L2-normalized over 2F
        float v1 = xv * bias[t];
        float v2 = v * bias[F + t];
        red[t] = v1 * v1 + v2 * v2; __syncthreads();
        for (int s = F / 2; s > 0; s >>= 1) { if (t < s) red[t] += red[t + s]; __syncthreads(); }
        float inv = 1.f / (sqrtf(red[0]) + Eps);
        out[(size_t)r * (2 * F) + t]     = tf32f(v1 * inv);
        out[(size_t)r * (2 * F) + F + t] = tf32f(v2 * inv);
    }
}

// ---------------- NT GEMM: TF32 mma (pre-rounded inputs), cp.async double buffer ----------------
// C[M,Nc] = A[M,Kk] * B[Nc,Kk]^T. grid (Nc/128, M/128, batch); z==1 -> A2/C2.
template<bool FUSE>
__global__ __launch_bounds__(256)
void mma_nt_k(const float* __restrict__ A, const float* __restrict__ A2,
              const float* __restrict__ B,
              float* C, float* C2, float* __restrict__ gs, float* __restrict__ gdiag,
              int Kk, int Nc, int sym) {
    extern __shared__ uint32_t dsm[];
    float* rowsum = (float*)(dsm + 2 * 2 * 4608);

    int bx = blockIdx.x, by = blockIdx.y;
    if (sym && by > bx) return;
    if (blockIdx.z == 1) { A = A2; C = C2; }
    int brow = by * 128, bcol = bx * 128;
    int tid = threadIdx.x;
    int lane = tid & 31, wid = tid >> 5;
    int g = lane >> 2, tg = lane & 3;
    int lrow = lane & 7, lhalf = (lane >> 3) & 1, lcol = lane >> 4;
    int wm = (wid >> 1) * 32, wn = (wid & 1) * 64;
    int nch = Kk >> 5;
    uint32_t smb = smem_u32(dsm);

    auto issue = [&](int st, int c) {
        #pragma unroll
        for (int l = 0; l < 8; l++) {
            int id = l * 256 + tid;
            int arr = id >> 10;               // 0:A 1:B
            int rem = id & 1023;
            int row = rem >> 3, seg = rem & 7;
            const float* gp = arr ? B : A;
            int rb = arr ? bcol : brow;
            const float* src = gp + (size_t)(rb + row) * Kk + c * 32 + seg * 4;
            uint32_t dst = smb + ((st * 2 + arr) * 4608 + row * 36 + seg * 4) * 4;
            cpa16(dst, src);
        }
        CP_COMMIT();
    };

    float acc[2][8][4];
    #pragma unroll
    for (int mt = 0; mt < 2; mt++)
        #pragma unroll
        for (int nt = 0; nt < 8; nt++)
            #pragma unroll
            for (int q = 0; q < 4; q++) acc[mt][nt][q] = 0.f;

    issue(0, 0);
    issue(1, 1);

    for (int c = 0; c < nch; c++) {
        if (c + 1 < nch) asm volatile("cp.async.wait_group 1;" ::: "memory");
        else             asm volatile("cp.async.wait_group 0;" ::: "memory");
        __syncthreads();
        int st = c & 1;
        uint32_t bA = smb + (st * 2 + 0) * 18432;
        uint32_t bB = smb + (st * 2 + 1) * 18432;
        #pragma unroll
        for (int k8 = 0; k8 < 4; k8++) {
            int cb = k8 * 8 + lcol * 4;
            uint32_t af[2][4];
            #pragma unroll
            for (int mt = 0; mt < 2; mt++) {
                uint32_t off = bA + ((wm + mt * 16 + lrow + lhalf * 8) * 36 + cb) * 4;
                LDMX4(af[mt][0], af[mt][1], af[mt][2], af[mt][3], off);
            }
            uint32_t bf[8][2];
            #pragma unroll
            for (int np = 0; np < 4; np++) {
                uint32_t off = bB + ((wn + np * 16 + lrow + lhalf * 8) * 36 + cb) * 4;
                uint32_t t0, t1, t2, t3;
                LDMX4(t0, t1, t2, t3, off);
                bf[np * 2][0]     = t0; bf[np * 2][1]     = t2;
                bf[np * 2 + 1][0] = t1; bf[np * 2 + 1][1] = t3;
            }
            #pragma unroll
            for (int mt = 0; mt < 2; mt++)
                #pragma unroll
                for (int nt = 0; nt < 8; nt++)
                    mma_tf32(acc[mt][nt], af[mt], bf[nt]);
        }
        __syncthreads();
        if (c + 2 < nch) issue(st, c + 2);
    }

    if (!FUSE) {
        #pragma unroll
        for (int mt = 0; mt < 2; mt++)
            #pragma unroll
            for (int nt = 0; nt < 8; nt++) {
                int r0 = brow + wm + mt * 16 + g;
                int c0 = bcol + wn + nt * 8 + 2 * tg;
                *(float2*)(C + (size_t)r0 * Nc + c0)       = make_float2(acc[mt][nt][0], acc[mt][nt][1]);
                *(float2*)(C + (size_t)(r0 + 8) * Nc + c0) = make_float2(acc[mt][nt][2], acc[mt][nt][3]);
            }
        if (sym && bx != by) {
            float (*Tb)[130] = (float(*)[130])dsm;    // 64 x 130 staging
            #pragma unroll
            for (int h = 0; h < 2; h++) {
                __syncthreads();
                if ((wid & 1) == h) {
                    #pragma unroll
                    for (int mt = 0; mt < 2; mt++)
                        #pragma unroll
                        for (int nt = 0; nt < 8; nt++) {
                            int rr = wm + mt * 16 + g;
                            int cl = nt * 8 + 2 * tg;
                            Tb[cl][rr]         = acc[mt][nt][0];
                            Tb[cl + 1][rr]     = acc[mt][nt][1];
                            Tb[cl][rr + 8]     = acc[mt][nt][2];
                            Tb[cl + 1][rr + 8] = acc[mt][nt][3];
                        }
                }
                __syncthreads();
                #pragma unroll
                for (int it = 0; it < 8; it++) {
                    int idx = tid + it * 256;
                    int rloc = idx >> 5, q = idx & 31;
                    float4 v = make_float4(Tb[rloc][4 * q], Tb[rloc][4 * q + 1],
                                           Tb[rloc][4 * q + 2], Tb[rloc][4 * q + 3]);
                    *(float4*)(C + (size_t)(bcol + h * 64 + rloc) * Nc + brow + 4 * q) = v;
                }
            }
        }
    } else {
        if (tid < 128) rowsum[tid] = 0.f;
        __syncthreads();
        #pragma unroll
        for (int mt = 0; mt < 2; mt++) {
            int lr0 = wm + mt * 16 + g;
            int gr0 = brow + lr0;
            float rs0 = 0.f, rs1 = 0.f;
            #pragma unroll
            for (int nt = 0; nt < 8; nt++) {
                int gc = bcol + wn + nt * 8 + 2 * tg;
                float e0 = fexp(InvT * acc[mt][nt][0]);
                float e1 = fexp(InvT * acc[mt][nt][1]);
                float e2 = fexp(InvT * acc[mt][nt][2]);
                float e3 = fexp(InvT * acc[mt][nt][3]);
                rs0 += e0 + e1;
                rs1 += e2 + e3;
                if (gc == gr0)         gdiag[gr0] = e0;
                if (gc + 1 == gr0)     gdiag[gr0] = e1;
                if (gc == gr0 + 8)     gdiag[gr0 + 8] = e2;
                if (gc + 1 == gr0 + 8) gdiag[gr0 + 8] = e3;
            }
            rs0 += __shfl_xor_sync(0xffffffffu, rs0, 1);
            rs0 += __shfl_xor_sync(0xffffffffu, rs0, 2);
            rs1 += __shfl_xor_sync(0xffffffffu, rs1, 1);
            rs1 += __shfl_xor_sync(0xffffffffu, rs1, 2);
            if (tg == 0) {
                atomicAdd(&rowsum[lr0], rs0);
                atomicAdd(&rowsum[lr0 + 8], rs1);
            }
        }
        __syncthreads();
        if (tid < 128) atomicAdd(&gs[brow + tid], rowsum[tid]);
    }
}

// ---------------- top-k (iterative argmax with cached local maxima) ----------------
__global__ void topk_k(const float* __restrict__ sim, int* topi, float* topv) {
    __shared__ float sv[Nv];
    __shared__ float lv[256];
    __shared__ int   li[256];
    __shared__ float wv[8];
    __shared__ int   wi[8];
    int r = blockIdx.x, t = threadIdx.x;
    float best = -1e30f; int besti = 1 << 30;
    #pragma unroll
    for (int q = 0; q < 16; q++) {
        int i = t + q * 256;
        float v = sim[(size_t)r * Nv + i];
        sv[i] = v;
        if (v > best) { best = v; besti = i; }
    }
    lv[t] = best; li[t] = besti;
    __syncthreads();
    for (int k = 0; k < Kp; k++) {
        float b = lv[t]; int bi = li[t];
        #pragma unroll
        for (int o = 16; o > 0; o >>= 1) {
            float ov = __shfl_down_sync(0xffffffffu, b, o);
            int   oi = __shfl_down_sync(0xffffffffu, bi, o);
            if (ov > b || (ov == b && oi < bi)) { b = ov; bi = oi; }
        }
        if ((t & 31) == 0) { wv[t >> 5] = b; wi[t >> 5] = bi; }
        __syncthreads();
        if (t == 0) {
            float bb = wv[0]; int bj = wi[0];
            #pragma unroll
            for (int w = 1; w < 8; w++)
                if (wv[w] > bb || (wv[w] == bb && wi[w] < bj)) { bb = wv[w]; bj = wi[w]; }
            topv[r * Kp + k] = bb;
            topi[r * Kp + k] = bj;
            sv[bj] = -1e30f;
            wi[0] = bj;
        }
        __syncthreads();
        int bj = wi[0];
        if ((bj & 255) == t) {
            float nb = -1e30f; int ni = 1 << 30;
            #pragma unroll
            for (int q = 0; q < 16; q++) {
                int i = t + q * 256;
                float v = sv[i];
                if (v > nb) { nb = v; ni = i; }
            }
            lv[t] = nb; li[t] = ni;
        }
        __syncthreads();
    }
}

// ---------------- hash-based symmetric Wund ----------------
__global__ void hash_ins_k(const int* ti, const float* tv,
                           int* hkey, float* hsum, int* hcnt) {
    int e = blockIdx.x * blockDim.x + threadIdx.x;
    if (e >= Nv * Kp) return;
    int r = e / Kp, c = ti[e];
    float v = tv[e];
    if (v != v) v = 0.f;
    int i = min(r, c), j = max(r, c);
    int key = (i << 12) | j;
    uint32_t slot = ((uint32_t)key * 2654435761u) >> 14;
    slot &= (HCAP - 1);
    while (true) {
        int old = atomicCAS(&hkey[slot], -1, key);
        if (old == -1 || old == key) break;
        slot = (slot + 1) & (HCAP - 1);
    }
    atomicAdd(&hsum[slot], v);
    atomicAdd(&hcnt[slot], 1);
}

__global__ void hash_emit_k(const int* hkey, const float* hsum, const int* hcnt,
                            int* cooi, int* cooj, float* coow, int* nnz, int* deg2) {
    int s = blockIdx.x * blockDim.x + threadIdx.x;
    if (s >= HCAP) return;
    int key = hkey[s];
    if (key < 0) return;
    float o = hsum[s] / (float)hcnt[s];
    if (o <= 0.f) return;
    int i = key >> 12, j = key & 4095;
    int p = atomicAdd(nnz, 1);
    cooi[p] = i; cooj[p] = j; coow[p] = o;
    atomicAdd(&deg2[i], 1);
    if (i != j) atomicAdd(&deg2[j], 1);
}

__global__ void scan2_k(const int* deg2, int* rowptr, int* fill) {
    __shared__ int s[1024];
    int t = threadIdx.x;
    int c[4]; int loc = 0;
    #pragma unroll
    for (int q = 0; q < 4; q++) { c[q] = deg2[t * 4 + q]; loc += c[q]; }
    s[t] = loc; __syncthreads();
    for (int off = 1; off < 1024; off <<= 1) {
        int v = (t >= off) ? s[t - off] : 0;
        __syncthreads();
        s[t] += v;
        __syncthreads();
    }
    int run = s[t] - loc;
    #pragma unroll
    for (int q = 0; q < 4; q++) {
        rowptr[t * 4 + q] = run; run += c[q];
        fill[t * 4 + q] = 0;
    }
    if (t == 1023) rowptr[Nv] = run;
}

__global__ void fill2_k(const int* cooi, const int* cooj, const float* coow,
                        const int* nnz, const int* rowptr, int* fill,
                        int* col2, float* w2) {
    int e = blockIdx.x * blockDim.x + threadIdx.x;
    if (e >= *nnz) return;
    int i = cooi[e], j = cooj[e];
    float o = coow[e];
    int p = rowptr[i] + atomicAdd(&fill[i], 1);
    col2[p] = j; w2[p] = o;
    if (i != j) {
        p = rowptr[j] + atomicAdd(&fill[j], 1);
        col2[p] = i; w2[p] = o;
    }
}

// ---------------- CSR SpMM for Wund ----------------
template<int EPI>
__global__ void spmm_csr_k(const int* __restrict__ rowptr, const int* __restrict__ col2,
                           const float* __restrict__ w2, const float* __restrict__ X,
                           const float* __restrict__ bias, float* __restrict__ out) {
    __shared__ int   sI[256];
    __shared__ float sW[256];
    __shared__ float red[256];
    int r = blockIdx.x, t = threadIdx.x;
    int beg = rowptr[r], end = rowptr[r + 1];
    float acc = 0.f;
    for (int base = beg; base < end; base += 256) {
        int m = min(256, end - base);
        if (t < m) { sI[t] = col2[base + t]; sW[t] = w2[base + t]; }
        __syncthreads();
        #pragma unroll 4
        for (int q = 0; q < m; q++) acc += sW[q] * X[(size_t)sI[q] * Dh + t];
        __syncthreads();
    }
    float v = acc + bias[t];
    if (EPI == 1) {
        out[(size_t)r * Dh + t] = tf32f(fmaxf(v, 0.f));
    } else {
        v = v > 0.f ? v : expm1f(v);
        red[t] = v * v; __syncthreads();
        for (int s = 128; s > 0; s >>= 1) { if (t < s) red[t] += red[t + s]; __syncthreads(); }
        out[(size_t)r * Dh + t] = tf32f(v / (sqrtf(red[0]) + Eps));
    }
}

// ---------------- pf/pb over COO nonzeros ----------------
__global__ void pfpb_k(const int* coo_i, const int* coo_j, const float* coo_w,
                       const int* nnz, const float* __restrict__ z1,
                       const float* __restrict__ z2, const float* gs,
                       float* pf, float* pb) {
    int wid = (blockIdx.x * blockDim.x + threadIdx.x) >> 5;
    int lane = threadIdx.x & 31;
    if (wid >= *nnz) return;
    int i = coo_i[wid], j = coo_j[wid];
    float wt = coo_w[wid];
    float d1 = 0.f, d2 = 0.f;
    #pragma unroll
    for (int q = 0; q < 8; q++) {
        int c = lane + q * 32;
        d1 += z1[(size_t)i * Dh + c] * z2[(size_t)j * Dh + c];
    }
    if (i != j) {
        #pragma unroll
        for (int q = 0; q < 8; q++) {
            int c = lane + q * 32;
            d2 += z1[(size_t)j * Dh + c] * z2[(size_t)i * Dh + c];
        }
    }
    #pragma unroll
    for (int o = 16; o > 0; o >>= 1) {
        d1 += __shfl_xor_sync(0xffffffffu, d1, o);
        d2 += __shfl_xor_sync(0xffffffffu, d2, o);
    }
    if (lane == 0) {
        float q1 = fexp(InvT * d1) / gs[i] * wt;
        atomicAdd(&pf[i], q1);
        atomicAdd(&pb[j], q1);
        if (i != j) {
            float q2 = fexp(InvT * d2) / gs[j] * wt;
            atomicAdd(&pf[j], q2);
            atomicAdd(&pb[i], q2);
        }
    }
}

__global__ void loss_k(const float* gdiag, const float* gs,
                       const float* pf, const float* pb, float* out) {
    __shared__ float s1[256], s2[256], s3[256];
    int t = threadIdx.x;
    float a = 0.f, b = 0.f, c = 0.f;
    for (int i = t; i < Nv; i += 256) {
        a -= logf(fmaxf(gdiag[i] / gs[i], Eps));
        b -= logf(fmaxf(pf[i], Eps));
        c -= logf(fmaxf(pb[i], Eps));
    }
    s1[t] = a; s2[t] = b; s3[t] = c; __syncthreads();
    for (int st = 128; st > 0; st >>= 1) {
        if (t < st) { s1[t] += s1[t + st]; s2[t] += s2[t + st]; s3[t] += s3[t + st]; }
        __syncthreads();
    }
    if (t == 0) out[0] = s1[0] / Nv + 0.5f * (s2[0] / Nv + s3[0] / Nv);
}

// ---------------- host launcher ----------------
extern "C" void kernel_launch(void* const* d_in, const int* in_sizes, int n_in,
                              void* d_out, int out_size) {
    const float* x       = (const float*)d_in[0];
    const int*   esrc    = (const int*)d_in[1];
    const int*   edst    = (const int*)d_in[2];
    const float* p_feat  = (const float*)d_in[3];
    const float* p_share = (const float*)d_in[4];
    const float* p_bal   = (const float*)d_in[5];
    const float* W1      = (const float*)d_in[6];
    const float* b1      = (const float*)d_in[7];
    const float* W2      = (const float*)d_in[8];
    const float* b2      = (const float*)d_in[9];
    float* out = (float*)d_out;
    int E = in_sizes[1];

    float* H = nullptr;
    cudaGetSymbolAddress((void**)&H, g_heap);
    float* sim  = H + O_SIM;
    float* x1   = H + O_X1;   float* hn  = H + O_HN;
    float* xw1  = H + O_XW1;  float* h1   = H + O_H1;   float* g1  = H + O_G1;
    float* bufB = H + O_BUFB; float* bufB2 = H + O_BUFB2;
    float* z1   = H + O_Z1;   float* z2   = H + O_Z2;
    float* w1t  = H + O_W1T;  float* w2t  = H + O_W2T;
    float* deg  = H + O_DEG;  float* dinv = H + O_DINV;
    float* gs   = H + O_GS;   float* pf   = H + O_PF;   float* pb  = H + O_PB;
    float* gd   = H + O_GD;
    int*   rptr = (int*)(H + O_RPTR);
    int*   fill = (int*)(H + O_FILL);
    int*   csrc = (int*)(H + O_CSRC);
    int*   topi = (int*)(H + O_TOPI);
    float* topv = H + O_TOPV;
    int*   cooi = (int*)(H + O_COOI);
    int*   cooj = (int*)(H + O_COOJ);
    float* coow = H + O_COOW;
    int*   nnz  = (int*)(H + O_NNZ);
    int*   hkey = (int*)(H + O_HKEY);
    float* hsum = H + O_HSUM;
    int*   hcnt = (int*)(H + O_HCNT);
    int*   deg2 = (int*)(H + O_DEG2);
    int*   rpt2 = (int*)(H + O_RPT2);
    int*   fil2 = (int*)(H + O_FIL2);
    int*   col2 = (int*)(H + O_COL2);
    float* wcs2 = H + O_WCS2;

    cudaFuncSetAttribute(mma_nt_k<false>, cudaFuncAttributeMaxDynamicSharedMemorySize, SMEM_DYN);
    cudaFuncSetAttribute(mma_nt_k<true>,  cudaFuncAttributeMaxDynamicSharedMemorySize, SMEM_DYN);

    // fused init + x1, then CSR build
    init_k<<<(Nv * Din) / 256, 256>>>(deg, hkey, hsum, hcnt, deg2, nnz, gs,
                                      x, p_feat, p_share, x1);
    deg_count_k<<<(E + 255) / 256, 256>>>(edst, deg, E);
    scan_k<<<1, 1024>>>(deg, dinv, rptr, fill);
    fill_k<<<(E + 255) / 256, 256>>>(esrc, edst, rptr, fill, csrc, E);

    // propagate + fused hn
    prop_k<Din, 3><<<Nv, Din>>>(x1, rptr, csrc, dinv, p_bal, hn);

    // weights transpose (fused)
    transpose2_k<<<dim3(Dh / 32, Dh / 32, 2), dim3(32, 32)>>>(W1, W2, w1t, w2t);

    // xw1 = x1 @ W1
    mma_nt_k<false><<<dim3(2, 32, 1), 256, SMEM_DYN>>>(
        x1, nullptr, w1t, xw1, nullptr, nullptr, nullptr, Din, Dh, 0);

    // sim = hn @ hn^T (symmetric, tf32)
    mma_nt_k<false><<<dim3(32, 32, 1), 256, SMEM_DYN>>>(
        hn, nullptr, hn, sim, nullptr, nullptr, nullptr, Dh, Nv, 1);

    // top-k -> hash -> CSR2
    topk_k<<<Nv, 256>>>(sim, topi, topv);
    hash_ins_k<<<(Nv * Kp + 255) / 256, 256>>>(topi, topv, hkey, hsum, hcnt);
    hash_emit_k<<<HCAP / 256, 256>>>(hkey, hsum, hcnt, cooi, cooj, coow, nnz, deg2);
    scan2_k<<<1, 1024>>>(deg2, rpt2, fil2);
    fill2_k<<<(Nv * Kp + 255) / 256, 256>>>(cooi, cooj, coow, nnz, rpt2, fil2, col2, wcs2);

    // layer-1 propagates (both views), batched W2 GEMM, layer-2 propagates
    prop_k<Dh, 1><<<Nv, Dh>>>(xw1, rptr, csrc, dinv, b1, h1);
    spmm_csr_k<1><<<Nv, Dh>>>(rpt2, col2, wcs2, xw1, b1, g1);
    mma_nt_k<false><<<dim3(2, 32, 2), 256, SMEM_DYN>>>(
        h1, g1, w2t, bufB, bufB2, nullptr, nullptr, Dh, Dh, 0);
    prop_k<Dh, 2><<<Nv, Dh>>>(bufB, rptr, csrc, dinv, b2, z1);
    spmm_csr_k<2><<<Nv, Dh>>>(rpt2, col2, wcs2, bufB2, b2, z2);

    // fused z1n @ z2n^T: row exp-sums + diag
    mma_nt_k<true><<<dim3(32, 32, 1), 256, SMEM_DYN>>>(
        z1, nullptr, z2, nullptr, nullptr, gs, gd, Dh, Nv, 0);

    // pf/pb + loss (grid sized to true nnz upper bound Nv*Kp)
    pfpb_k<<<(Nv * Kp + 7) / 8, 256>>>(cooi, cooj, coow, nnz, z1, z2, gs, pf, pb);
    loss_k<<<1, 256>>>(gd, gs, pf, pb, out);
}

// round 13
// speedup vs baseline: 1.5422x; 1.0192x over previous
#include <cuda_runtime.h>
#include <math.h>
#include <stdint.h>

// ---------------- problem constants ----------------
namespace {
constexpr int    Nv   = 4096;
constexpr int    Din  = 128;
constexpr int    Dh   = 256;
constexpr int    Kp   = 17;          // K+1
constexpr float  Eps  = 1e-8f;
constexpr float  InvT = 5.0f;        // 1/TEMP
constexpr size_t NN   = (size_t)Nv * (size_t)Nv;
constexpr int    Emax = 131072;
constexpr int    HCAP = 1 << 18;
constexpr int    CSR2_CAP = 160000;

// scratch heap layout (units: floats)
constexpr size_t O_SIM  = 0;
constexpr size_t O_X1   = O_SIM + NN;
constexpr size_t O_HN   = O_X1  + (size_t)Nv*Din;
constexpr size_t O_XW1  = O_HN  + (size_t)Nv*Dh;
constexpr size_t O_H1   = O_XW1 + (size_t)Nv*Dh;
constexpr size_t O_G1   = O_H1  + (size_t)Nv*Dh;
constexpr size_t O_BUFB = O_G1  + (size_t)Nv*Dh;
constexpr size_t O_BUFB2= O_BUFB+ (size_t)Nv*Dh;
constexpr size_t O_Z1   = O_BUFB2+(size_t)Nv*Dh;
constexpr size_t O_Z2   = O_Z1  + (size_t)Nv*Dh;
constexpr size_t O_W1T  = O_Z2  + (size_t)Nv*Dh;       // [Dh][Din]
constexpr size_t O_W2T  = O_W1T + (size_t)Dh*Din;      // [Dh][Dh]
constexpr size_t O_DEG  = O_W2T + (size_t)Dh*Dh;
constexpr size_t O_DINV = O_DEG + Nv;
constexpr size_t O_GS   = O_DINV+ Nv;
constexpr size_t O_PF   = O_GS  + Nv;
constexpr size_t O_PB   = O_PF  + Nv;
constexpr size_t O_GD   = O_PB  + Nv;
constexpr size_t O_RPTR = O_GD  + Nv;
constexpr size_t O_FILL = O_RPTR+ (Nv + 4);
constexpr size_t O_CSRC = O_FILL+ Nv;
constexpr size_t O_TOPI = O_CSRC+ Emax;
constexpr size_t O_TOPV = O_TOPI+ (size_t)Nv*Kp;
constexpr size_t O_COOI = O_TOPV+ (size_t)Nv*Kp;
constexpr size_t O_COOJ = O_COOI+ (size_t)Nv*Kp;
constexpr size_t O_COOW = O_COOJ+ (size_t)Nv*Kp;
constexpr size_t O_NNZ  = O_COOW+ (size_t)Nv*Kp;
constexpr size_t O_HKEY = O_NNZ + 4;
constexpr size_t O_HSUM = O_HKEY+ HCAP;
constexpr size_t O_HCNT = O_HSUM+ HCAP;
constexpr size_t O_DEG2 = O_HCNT+ HCAP;
constexpr size_t O_RPT2 = O_DEG2+ Nv;
constexpr size_t O_FIL2 = O_RPT2+ (Nv + 4);
constexpr size_t O_COL2 = O_FIL2+ Nv;
constexpr size_t O_WCS2 = O_COL2+ CSR2_CAP;
constexpr size_t TOTAL  = O_WCS2+ CSR2_CAP;

// GEMM smem: 2 stages x 2 arrays x 128 rows x 36 u32 (32 data + 4 pad)
constexpr unsigned SMEM_DYN = (2 * 2 * 4608 + 128) * 4;
}

__device__ __align__(256) float g_heap[TOTAL];

// ---------------- fast exp (FMA only) ----------------
__device__ __forceinline__ float fexp(float x) {
    float t  = x * 1.4426950408889634f;
    float rf = __fadd_rn(t, 12582912.0f);
    int   e  = __float_as_int(rf) - 0x4B400000;
    float r  = __fadd_rn(rf, -12582912.0f);
    float f  = t - r;
    float p  = fmaf(1.5403530394e-4f, f, 1.3333558146e-3f);
    p = fmaf(p, f, 9.6181291076e-3f);
    p = fmaf(p, f, 5.5504108665e-2f);
    p = fmaf(p, f, 2.4022650696e-1f);
    p = fmaf(p, f, 6.9314718056e-1f);
    p = fmaf(p, f, 1.0f);
    return __int_as_float(__float_as_int(p) + (e << 23));
}

// ---------------- tf32 helpers ----------------
__device__ __forceinline__ float tf32f(float x) {
    uint32_t r;
    asm("cvt.rna.tf32.f32 %0, %1;" : "=r"(r) : "f"(x));
    return __uint_as_float(r);
}
__device__ __forceinline__ void mma_tf32(float* c, const uint32_t* a, const uint32_t* b) {
    asm volatile(
        "mma.sync.aligned.m16n8k8.row.col.f32.tf32.tf32.f32 "
        "{%0,%1,%2,%3}, {%4,%5,%6,%7}, {%8,%9}, {%0,%1,%2,%3};"
        : "+f"(c[0]), "+f"(c[1]), "+f"(c[2]), "+f"(c[3])
        : "r"(a[0]), "r"(a[1]), "r"(a[2]), "r"(a[3]), "r"(b[0]), "r"(b[1]));
}
__device__ __forceinline__ uint32_t smem_u32(const void* p) {
    uint32_t a;
    asm("{ .reg .u64 t; cvta.to.shared.u64 t, %1; cvt.u32.u64 %0, t; }" : "=r"(a) : "l"(p));
    return a;
}
__device__ __forceinline__ void cpa16(uint32_t dst, const void* src) {
    asm volatile("cp.async.cg.shared.global [%0], [%1], 16;" :: "r"(dst), "l"(src));
}
#define CP_COMMIT() asm volatile("cp.async.commit_group;" ::: "memory")
#define LDMX4(r0, r1, r2, r3, addr) \
    asm volatile("ldmatrix.sync.aligned.m8n8.x4.shared.b16 {%0,%1,%2,%3}, [%4];" \
        : "=r"(r0), "=r"(r1), "=r"(r2), "=r"(r3) : "r"(addr))

// streaming (evict-first) global access for dead-after-use data
__device__ __forceinline__ void stg_cs_f2(float* p, float2 v) {
    asm volatile("st.global.cs.v2.f32 [%0], {%1, %2};" :: "l"(p), "f"(v.x), "f"(v.y) : "memory");
}
__device__ __forceinline__ void stg_cs_f4(float* p, float4 v) {
    asm volatile("st.global.cs.v4.f32 [%0], {%1, %2, %3, %4};"
                 :: "l"(p), "f"(v.x), "f"(v.y), "f"(v.z), "f"(v.w) : "memory");
}
__device__ __forceinline__ float ldg_cs(const float* p) {
    float v;
    asm volatile("ld.global.cs.f32 %0, [%1];" : "=f"(v) : "l"(p));
    return v;
}

// ---------------- init (fused with x1 compute) ----------------
__global__ void init_k(float* deg, int* hkey, float* hsum, int* hcnt,
                       int* deg2, int* nnz, float* gs3,
                       const float* __restrict__ x, const float* __restrict__ pf,
                       const float* __restrict__ ps, float* __restrict__ x1) {
    int i = blockIdx.x * blockDim.x + threadIdx.x;     // 0 .. Nv*Din-1 (524288)
    if (i < HCAP) { hkey[i] = -1; hsum[i] = 0.f; hcnt[i] = 0; }
    if (i < Nv) { deg[i] = 1.f; deg2[i] = 0; }
    if (i < Nv * 3) gs3[i] = 0.f;
    if (i == 0) nnz[0] = 0;
    int c = i % Din;
    float v = x[i] * pf[c];
    x1[i] = tf32f(fmaxf(v, 0.f) * ps[c]);
}

__global__ void deg_count_k(const int* dst, float* deg, int E) {
    int e = blockIdx.x * blockDim.x + threadIdx.x;
    if (e < E) atomicAdd(&deg[dst[e]], 1.f);
}

// both weight transposes in one launch: z=0 -> W1 [Din,Dh], z=1 -> W2 [Dh,Dh]
__global__ void transpose2_k(const float* __restrict__ W1, const float* __restrict__ W2,
                             float* __restrict__ w1t, float* __restrict__ w2t) {
    __shared__ float tile[32][33];
    int z = blockIdx.z;
    int R  = z ? Dh : Din;
    const float* A = z ? W2 : W1;
    float* AT = z ? w2t : w1t;
    if (!z && blockIdx.y >= Din / 32) return;
    int x = blockIdx.x * 32 + threadIdx.x;
    int y = blockIdx.y * 32 + threadIdx.y;
    tile[threadIdx.y][threadIdx.x] = A[(size_t)y * Dh + x];
    __syncthreads();
    int xo = blockIdx.y * 32 + threadIdx.x;
    int yo = blockIdx.x * 32 + threadIdx.y;
    AT[(size_t)yo * R + xo] = tf32f(tile[threadIdx.x][threadIdx.y]);
}

// ---------------- CSR build (original graph) ----------------
__global__ void scan_k(const float* deg, float* dinv, int* rowptr, int* fill) {
    __shared__ int s[1024];
    int t = threadIdx.x;
    int c[4]; int loc = 0;
    #pragma unroll
    for (int q = 0; q < 4; q++) {
        float d = deg[t * 4 + q];
        dinv[t * 4 + q] = rsqrtf(d);
        c[q] = (int)d - 1; loc += c[q];
    }
    s[t] = loc; __syncthreads();
    for (int off = 1; off < 1024; off <<= 1) {
        int v = (t >= off) ? s[t - off] : 0;
        __syncthreads();
        s[t] += v;
        __syncthreads();
    }
    int run = s[t] - loc;
    #pragma unroll
    for (int q = 0; q < 4; q++) {
        rowptr[t * 4 + q] = run; run += c[q];
        fill[t * 4 + q] = 0;
    }
    if (t == 1023) rowptr[Nv] = run;
}

__global__ void fill_k(const int* es, const int* ed, const int* rowptr,
                       int* fill, int* csrc, int E) {
    int e = blockIdx.x * blockDim.x + threadIdx.x;
    if (e >= E) return;
    int d = ed[e];
    int p = rowptr[d] + atomicAdd(&fill[d], 1);
    csrc[p] = es[e];
}

// ---------------- CSR gather propagate ----------------
// EPI 0: plain. EPI 1: relu+bias (tf32). EPI 2: elu+bias+norm (tf32).
// EPI 3 (F=Din): fused hn epilogue -> out is hn [Nv, Dh], bias is p_balance[2*Din].
template<int F, int EPI>
__global__ void prop_k(const float* __restrict__ X, const int* __restrict__ rowptr,
                       const int* __restrict__ csrc, const float* __restrict__ dinv,
                       const float* __restrict__ bias, float* __restrict__ out) {
    __shared__ int   sI[F];
    __shared__ float sW[F];
    __shared__ float red[(EPI >= 2) ? F : 1];
    int r = blockIdx.x, t = threadIdx.x;
    int beg = rowptr[r], end = rowptr[r + 1];
    float acc = 0.f;
    for (int base = beg; base < end; base += F) {
        int m = min(F, end - base);
        if (t < m) { int s = csrc[base + t]; sI[t] = s; sW[t] = dinv[s]; }
        __syncthreads();
        #pragma unroll 4
        for (int q = 0; q < m; q++) acc += sW[q] * X[(size_t)sI[q] * F + t];
        __syncthreads();
    }
    float dv = dinv[r];
    float xv = X[(size_t)r * F + t];
    float v = dv * dv * xv + dv * acc;
    if (EPI == 0) {
        out[(size_t)r * F + t] = v;
    } else if (EPI == 1) {
        out[(size_t)r * F + t] = tf32f(fmaxf(v + bias[t], 0.f));
    } else if (EPI == 2) {
        v += bias[t];
        v = v > 0.f ? v : expm1f(v);
        red[t] = v * v; __syncthreads();
        for (int s = F / 2; s > 0; s >>= 1) { if (t < s) red[t] += red[t + s]; __syncthreads(); }
        out[(size_t)r * F + t] = tf32f(v / (sqrtf(red[0]) + Eps));
    } else {
        // fused hn: h = [x1, agg] * p_balance, L2-normalized over 2F
        float v1 = xv * bias[t];
        float v2 = v * bias[F + t];
        red[t] = v1 * v1 + v2 * v2; __syncthreads();
        for (int s = F / 2; s > 0; s >>= 1) { if (t < s) red[t] += red[t + s]; __syncthreads(); }
        float inv = 1.f / (sqrtf(red[0]) + Eps);
        out[(size_t)r * (2 * F) + t]     = tf32f(v1 * inv);
        out[(size_t)r * (2 * F) + F + t] = tf32f(v2 * inv);
    }
}

// ---------------- NT GEMM: TF32 mma (pre-rounded inputs), cp.async double buffer ----------------
// C[M,Nc] = A[M,Kk] * B[Nc,Kk]^T. grid (Nc/128, M/128, batch); z==1 -> A2/C2.
// STREAMC: evict-first stores for dead-after-one-read C (sim).
template<bool FUSE, bool STREAMC>
__global__ __launch_bounds__(256)
void mma_nt_k(const float* __restrict__ A, const float* __restrict__ A2,
              const float* __restrict__ B,
              float* C, float* C2, float* __restrict__ gs, float* __restrict__ gdiag,
              int Kk, int Nc, int sym) {
    extern __shared__ uint32_t dsm[];
    float* rowsum = (float*)(dsm + 2 * 2 * 4608);

    int bx = blockIdx.x, by = blockIdx.y;
    if (sym && by > bx) return;
    if (blockIdx.z == 1) { A = A2; C = C2; }
    int brow = by * 128, bcol = bx * 128;
    int tid = threadIdx.x;
    int lane = tid & 31, wid = tid >> 5;
    int g = lane >> 2, tg = lane & 3;
    int lrow = lane & 7, lhalf = (lane >> 3) & 1, lcol = lane >> 4;
    int wm = (wid >> 1) * 32, wn = (wid & 1) * 64;
    int nch = Kk >> 5;
    uint32_t smb = smem_u32(dsm);

    auto issue = [&](int st, int c) {
        #pragma unroll
        for (int l = 0; l < 8; l++) {
            int id = l * 256 + tid;
            int arr = id >> 10;               // 0:A 1:B
            int rem = id & 1023;
            int row = rem >> 3, seg = rem & 7;
            const float* gp = arr ? B : A;
            int rb = arr ? bcol : brow;
            const float* src = gp + (size_t)(rb + row) * Kk + c * 32 + seg * 4;
            uint32_t dst = smb + ((st * 2 + arr) * 4608 + row * 36 + seg * 4) * 4;
            cpa16(dst, src);
        }
        CP_COMMIT();
    };

    float acc[2][8][4];
    #pragma unroll
    for (int mt = 0; mt < 2; mt++)
        #pragma unroll
        for (int nt = 0; nt < 8; nt++)
            #pragma unroll
            for (int q = 0; q < 4; q++) acc[mt][nt][q] = 0.f;

    issue(0, 0);
    issue(1, 1);

    for (int c = 0; c < nch; c++) {
        if (c + 1 < nch) asm volatile("cp.async.wait_group 1;" ::: "memory");
        else             asm volatile("cp.async.wait_group 0;" ::: "memory");
        __syncthreads();
        int st = c & 1;
        uint32_t bA = smb + (st * 2 + 0) * 18432;
        uint32_t bB = smb + (st * 2 + 1) * 18432;
        #pragma unroll
        for (int k8 = 0; k8 < 4; k8++) {
            int cb = k8 * 8 + lcol * 4;
            uint32_t af[2][4];
            #pragma unroll
            for (int mt = 0; mt < 2; mt++) {
                uint32_t off = bA + ((wm + mt * 16 + lrow + lhalf * 8) * 36 + cb) * 4;
                LDMX4(af[mt][0], af[mt][1], af[mt][2], af[mt][3], off);
            }
            uint32_t bf[8][2];
            #pragma unroll
            for (int np = 0; np < 4; np++) {
                uint32_t off = bB + ((wn + np * 16 + lrow + lhalf * 8) * 36 + cb) * 4;
                uint32_t t0, t1, t2, t3;
                LDMX4(t0, t1, t2, t3, off);
                bf[np * 2][0]     = t0; bf[np * 2][1]     = t2;
                bf[np * 2 + 1][0] = t1; bf[np * 2 + 1][1] = t3;
            }
            #pragma unroll
            for (int mt = 0; mt < 2; mt++)
                #pragma unroll
                for (int nt = 0; nt < 8; nt++)
                    mma_tf32(acc[mt][nt], af[mt], bf[nt]);
        }
        __syncthreads();
        if (c + 2 < nch) issue(st, c + 2);
    }

    if (!FUSE) {
        #pragma unroll
        for (int mt = 0; mt < 2; mt++)
            #pragma unroll
            for (int nt = 0; nt < 8; nt++) {
                int r0 = brow + wm + mt * 16 + g;
                int c0 = bcol + wn + nt * 8 + 2 * tg;
                float2 v01 = make_float2(acc[mt][nt][0], acc[mt][nt][1]);
                float2 v23 = make_float2(acc[mt][nt][2], acc[mt][nt][3]);
                if (STREAMC) {
                    stg_cs_f2(C + (size_t)r0 * Nc + c0, v01);
                    stg_cs_f2(C + (size_t)(r0 + 8) * Nc + c0, v23);
                } else {
                    *(float2*)(C + (size_t)r0 * Nc + c0)       = v01;
                    *(float2*)(C + (size_t)(r0 + 8) * Nc + c0) = v23;
                }
            }
        if (sym && bx != by) {
            float (*Tb)[130] = (float(*)[130])dsm;    // 64 x 130 staging
            #pragma unroll
            for (int h = 0; h < 2; h++) {
                __syncthreads();
                if ((wid & 1) == h) {
                    #pragma unroll
                    for (int mt = 0; mt < 2; mt++)
                        #pragma unroll
                        for (int nt = 0; nt < 8; nt++) {
                            int rr = wm + mt * 16 + g;
                            int cl = nt * 8 + 2 * tg;
                            Tb[cl][rr]         = acc[mt][nt][0];
                            Tb[cl + 1][rr]     = acc[mt][nt][1];
                            Tb[cl][rr + 8]     = acc[mt][nt][2];
                            Tb[cl + 1][rr + 8] = acc[mt][nt][3];
                        }
                }
                __syncthreads();
                #pragma unroll
                for (int it = 0; it < 8; it++) {
                    int idx = tid + it * 256;
                    int rloc = idx >> 5, q = idx & 31;
                    float4 v = make_float4(Tb[rloc][4 * q], Tb[rloc][4 * q + 1],
                                           Tb[rloc][4 * q + 2], Tb[rloc][4 * q + 3]);
                    if (STREAMC)
                        stg_cs_f4(C + (size_t)(bcol + h * 64 + rloc) * Nc + brow + 4 * q, v);
                    else
                        *(float4*)(C + (size_t)(bcol + h * 64 + rloc) * Nc + brow + 4 * q) = v;
                }
            }
        }
    } else {
        if (tid < 128) rowsum[tid] = 0.f;
        __syncthreads();
        #pragma unroll
        for (int mt = 0; mt < 2; mt++) {
            int lr0 = wm + mt * 16 + g;
            int gr0 = brow + lr0;
            float rs0 = 0.f, rs1 = 0.f;
            #pragma unroll
            for (int nt = 0; nt < 8; nt++) {
                int gc = bcol + wn + nt * 8 + 2 * tg;
                float e0 = fexp(InvT * acc[mt][nt][0]);
                float e1 = fexp(InvT * acc[mt][nt][1]);
                float e2 = fexp(InvT * acc[mt][nt][2]);
                float e3 = fexp(InvT * acc[mt][nt][3]);
                rs0 += e0 + e1;
                rs1 += e2 + e3;
                if (gc == gr0)         gdiag[gr0] = e0;
                if (gc + 1 == gr0)     gdiag[gr0] = e1;
                if (gc == gr0 + 8)     gdiag[gr0 + 8] = e2;
                if (gc + 1 == gr0 + 8) gdiag[gr0 + 8] = e3;
            }
            rs0 += __shfl_xor_sync(0xffffffffu, rs0, 1);
            rs0 += __shfl_xor_sync(0xffffffffu, rs0, 2);
            rs1 += __shfl_xor_sync(0xffffffffu, rs1, 1);
            rs1 += __shfl_xor_sync(0xffffffffu, rs1, 2);
            if (tg == 0) {
                atomicAdd(&rowsum[lr0], rs0);
                atomicAdd(&rowsum[lr0 + 8], rs1);
            }
        }
        __syncthreads();
        if (tid < 128) atomicAdd(&gs[brow + tid], rowsum[tid]);
    }
}

// ---------------- top-k (iterative argmax with cached local maxima) ----------------
__global__ void topk_k(const float* __restrict__ sim, int* topi, float* topv) {
    __shared__ float sv[Nv];
    __shared__ float lv[256];
    __shared__ int   li[256];
    __shared__ float wv[8];
    __shared__ int   wi[8];
    int r = blockIdx.x, t = threadIdx.x;
    float best = -1e30f; int besti = 1 << 30;
    #pragma unroll
    for (int q = 0; q < 16; q++) {
        int i = t + q * 256;
        float v = ldg_cs(sim + (size_t)r * Nv + i);   // evict-first: sim is dead after this
        sv[i] = v;
        if (v > best) { best = v; besti = i; }
    }
    lv[t] = best; li[t] = besti;
    __syncthreads();
    for (int k = 0; k < Kp; k++) {
        float b = lv[t]; int bi = li[t];
        #pragma unroll
        for (int o = 16; o > 0; o >>= 1) {
            float ov = __shfl_down_sync(0xffffffffu, b, o);
            int   oi = __shfl_down_sync(0xffffffffu, bi, o);
            if (ov > b || (ov == b && oi < bi)) { b = ov; bi = oi; }
        }
        if ((t & 31) == 0) { wv[t >> 5] = b; wi[t >> 5] = bi; }
        __syncthreads();
        if (t == 0) {
            float bb = wv[0]; int bj = wi[0];
            #pragma unroll
            for (int w = 1; w < 8; w++)
                if (wv[w] > bb || (wv[w] == bb && wi[w] < bj)) { bb = wv[w]; bj = wi[w]; }
            topv[r * Kp + k] = bb;
            topi[r * Kp + k] = bj;
            sv[bj] = -1e30f;
            wi[0] = bj;
        }
        __syncthreads();
        int bj = wi[0];
        if ((bj & 255) == t) {
            float nb = -1e30f; int ni = 1 << 30;
            #pragma unroll
            for (int q = 0; q < 16; q++) {
                int i = t + q * 256;
                float v = sv[i];
                if (v > nb) { nb = v; ni = i; }
            }
            lv[t] = nb; li[t] = ni;
        }
        __syncthreads();
    }
}

// ---------------- hash-based symmetric Wund ----------------
__global__ void hash_ins_k(const int* ti, const float* tv,
                           int* hkey, float* hsum, int* hcnt) {
    int e = blockIdx.x * blockDim.x + threadIdx.x;
    if (e >= Nv * Kp) return;
    int r = e / Kp, c = ti[e];
    float v = tv[e];
    if (v != v) v = 0.f;
    int i = min(r, c), j = max(r, c);
    int key = (i << 12) | j;
    uint32_t slot = ((uint32_t)key * 2654435761u) >> 14;
    slot &= (HCAP - 1);
    while (true) {
        int old = atomicCAS(&hkey[slot], -1, key);
        if (old == -1 || old == key) break;
        slot = (slot + 1) & (HCAP - 1);
    }
    atomicAdd(&hsum[slot], v);
    atomicAdd(&hcnt[slot], 1);
}

__global__ void hash_emit_k(const int* hkey, const float* hsum, const int* hcnt,
                            int* cooi, int* cooj, float* coow, int* nnz, int* deg2) {
    int s = blockIdx.x * blockDim.x + threadIdx.x;
    if (s >= HCAP) return;
    int key = hkey[s];
    if (key < 0) return;
    float o = hsum[s] / (float)hcnt[s];
    if (o <= 0.f) return;
    int i = key >> 12, j = key & 4095;
    int p = atomicAdd(nnz, 1);
    cooi[p] = i; cooj[p] = j; coow[p] = o;
    atomicAdd(&deg2[i], 1);
    if (i != j) atomicAdd(&deg2[j], 1);
}

__global__ void scan2_k(const int* deg2, int* rowptr, int* fill) {
    __shared__ int s[1024];
    int t = threadIdx.x;
    int c[4]; int loc = 0;
    #pragma unroll
    for (int q = 0; q < 4; q++) { c[q] = deg2[t * 4 + q]; loc += c[q]; }
    s[t] = loc; __syncthreads();
    for (int off = 1; off < 1024; off <<= 1) {
        int v = (t >= off) ? s[t - off] : 0;
        __syncthreads();
        s[t] += v;
        __syncthreads();
    }
    int run = s[t] - loc;
    #pragma unroll
    for (int q = 0; q < 4; q++) {
        rowptr[t * 4 + q] = run; run += c[q];
        fill[t * 4 + q] = 0;
    }
    if (t == 1023) rowptr[Nv] = run;
}

__global__ void fill2_k(const int* cooi, const int* cooj, const float* coow,
                        const int* nnz, const int* rowptr, int* fill,
                        int* col2, float* w2) {
    int e = blockIdx.x * blockDim.x + threadIdx.x;
    if (e >= *nnz) return;
    int i = cooi[e], j = cooj[e];
    float o = coow[e];
    int p = rowptr[i] + atomicAdd(&fill[i], 1);
    col2[p] = j; w2[p] = o;
    if (i != j) {
        p = rowptr[j] + atomicAdd(&fill[j], 1);
        col2[p] = i; w2[p] = o;
    }
}

// ---------------- CSR SpMM for Wund ----------------
template<int EPI>
__global__ void spmm_csr_k(const int* __restrict__ rowptr, const int* __restrict__ col2,
                           const float* __restrict__ w2, const float* __restrict__ X,
                           const float* __restrict__ bias, float* __restrict__ out) {
    __shared__ int   sI[256];
    __shared__ float sW[256];
    __shared__ float red[256];
    int r = blockIdx.x, t = threadIdx.x;
    int beg = rowptr[r], end = rowptr[r + 1];
    float acc = 0.f;
    for (int base = beg; base < end; base += 256) {
        int m = min(256, end - base);
        if (t < m) { sI[t] = col2[base + t]; sW[t] = w2[base + t]; }
        __syncthreads();
        #pragma unroll 4
        for (int q = 0; q < m; q++) acc += sW[q] * X[(size_t)sI[q] * Dh + t];
        __syncthreads();
    }
    float v = acc + bias[t];
    if (EPI == 1) {
        out[(size_t)r * Dh + t] = tf32f(fmaxf(v, 0.f));
    } else {
        v = v > 0.f ? v : expm1f(v);
        red[t] = v * v; __syncthreads();
        for (int s = 128; s > 0; s >>= 1) { if (t < s) red[t] += red[t + s]; __syncthreads(); }
        out[(size_t)r * Dh + t] = tf32f(v / (sqrtf(red[0]) + Eps));
    }
}

// ---------------- pf/pb over COO nonzeros ----------------
__global__ void pfpb_k(const int* coo_i, const int* coo_j, const float* coo_w,
                       const int* nnz, const float* __restrict__ z1,
                       const float* __restrict__ z2, const float* gs,
                       float* pf, float* pb) {
    int wid = (blockIdx.x * blockDim.x + threadIdx.x) >> 5;
    int lane = threadIdx.x & 31;
    if (wid >= *nnz) return;
    int i = coo_i[wid], j = coo_j[wid];
    float wt = coo_w[wid];
    float d1 = 0.f, d2 = 0.f;
    #pragma unroll
    for (int q = 0; q < 8; q++) {
        int c = lane + q * 32;
        d1 += z1[(size_t)i * Dh + c] * z2[(size_t)j * Dh + c];
    }
    if (i != j) {
        #pragma unroll
        for (int q = 0; q < 8; q++) {
            int c = lane + q * 32;
            d2 += z1[(size_t)j * Dh + c] * z2[(size_t)i * Dh + c];
        }
    }
    #pragma unroll
    for (int o = 16; o > 0; o >>= 1) {
        d1 += __shfl_xor_sync(0xffffffffu, d1, o);
        d2 += __shfl_xor_sync(0xffffffffu, d2, o);
    }
    if (lane == 0) {
        float q1 = fexp(InvT * d1) / gs[i] * wt;
        atomicAdd(&pf[i], q1);
        atomicAdd(&pb[j], q1);
        if (i != j) {
            float q2 = fexp(InvT * d2) / gs[j] * wt;
            atomicAdd(&pf[j], q2);
            atomicAdd(&pb[i], q2);
        }
    }
}

__global__ void loss_k(const float* gdiag, const float* gs,
                       const float* pf, const float* pb, float* out) {
    __shared__ float s1[256], s2[256], s3[256];
    int t = threadIdx.x;
    float a = 0.f, b = 0.f, c = 0.f;
    for (int i = t; i < Nv; i += 256) {
        a -= logf(fmaxf(gdiag[i] / gs[i], Eps));
        b -= logf(fmaxf(pf[i], Eps));
        c -= logf(fmaxf(pb[i], Eps));
    }
    s1[t] = a; s2[t] = b; s3[t] = c; __syncthreads();
    for (int st = 128; st > 0; st >>= 1) {
        if (t < st) { s1[t] += s1[t + st]; s2[t] += s2[t + st]; s3[t] += s3[t + st]; }
        __syncthreads();
    }
    if (t == 0) out[0] = s1[0] / Nv + 0.5f * (s2[0] / Nv + s3[0] / Nv);
}

// ---------------- host launcher ----------------
extern "C" void kernel_launch(void* const* d_in, const int* in_sizes, int n_in,
                              void* d_out, int out_size) {
    const float* x       = (const float*)d_in[0];
    const int*   esrc    = (const int*)d_in[1];
    const int*   edst    = (const int*)d_in[2];
    const float* p_feat  = (const float*)d_in[3];
    const float* p_share = (const float*)d_in[4];
    const float* p_bal   = (const float*)d_in[5];
    const float* W1      = (const float*)d_in[6];
    const float* b1      = (const float*)d_in[7];
    const float* W2      = (const float*)d_in[8];
    const float* b2      = (const float*)d_in[9];
    float* out = (float*)d_out;
    int E = in_sizes[1];

    float* H = nullptr;
    cudaGetSymbolAddress((void**)&H, g_heap);
    float* sim  = H + O_SIM;
    float* x1   = H + O_X1;   float* hn  = H + O_HN;
    float* xw1  = H + O_XW1;  float* h1   = H + O_H1;   float* g1  = H + O_G1;
    float* bufB = H + O_BUFB; float* bufB2 = H + O_BUFB2;
    float* z1   = H + O_Z1;   float* z2   = H + O_Z2;
    float* w1t  = H + O_W1T;  float* w2t  = H + O_W2T;
    float* deg  = H + O_DEG;  float* dinv = H + O_DINV;
    float* gs   = H + O_GS;   float* pf   = H + O_PF;   float* pb  = H + O_PB;
    float* gd   = H + O_GD;
    int*   rptr = (int*)(H + O_RPTR);
    int*   fill = (int*)(H + O_FILL);
    int*   csrc = (int*)(H + O_CSRC);
    int*   topi = (int*)(H + O_TOPI);
    float* topv = H + O_TOPV;
    int*   cooi = (int*)(H + O_COOI);
    int*   cooj = (int*)(H + O_COOJ);
    float* coow = H + O_COOW;
    int*   nnz  = (int*)(H + O_NNZ);
    int*   hkey = (int*)(H + O_HKEY);
    float* hsum = H + O_HSUM;
    int*   hcnt = (int*)(H + O_HCNT);
    int*   deg2 = (int*)(H + O_DEG2);
    int*   rpt2 = (int*)(H + O_RPT2);
    int*   fil2 = (int*)(H + O_FIL2);
    int*   col2 = (int*)(H + O_COL2);
    float* wcs2 = H + O_WCS2;

    cudaFuncSetAttribute(mma_nt_k<false, false>, cudaFuncAttributeMaxDynamicSharedMemorySize, SMEM_DYN);
    cudaFuncSetAttribute(mma_nt_k<false, true>,  cudaFuncAttributeMaxDynamicSharedMemorySize, SMEM_DYN);
    cudaFuncSetAttribute(mma_nt_k<true, false>,  cudaFuncAttributeMaxDynamicSharedMemorySize, SMEM_DYN);

    // fused init + x1, then CSR build
    init_k<<<(Nv * Din) / 256, 256>>>(deg, hkey, hsum, hcnt, deg2, nnz, gs,
                                      x, p_feat, p_share, x1);
    deg_count_k<<<(E + 255) / 256, 256>>>(edst, deg, E);
    scan_k<<<1, 1024>>>(deg, dinv, rptr, fill);
    fill_k<<<(E + 255) / 256, 256>>>(esrc, edst, rptr, fill, csrc, E);

    // propagate + fused hn
    prop_k<Din, 3><<<Nv, Din>>>(x1, rptr, csrc, dinv, p_bal, hn);

    // weights transpose (fused)
    transpose2_k<<<dim3(Dh / 32, Dh / 32, 2), dim3(32, 32)>>>(W1, W2, w1t, w2t);

    // xw1 = x1 @ W1
    mma_nt_k<false, false><<<dim3(2, 32, 1), 256, SMEM_DYN>>>(
        x1, nullptr, w1t, xw1, nullptr, nullptr, nullptr, Din, Dh, 0);

    // sim = hn @ hn^T (symmetric, tf32, streaming stores — sim is read once then dead)
    mma_nt_k<false, true><<<dim3(32, 32, 1), 256, SMEM_DYN>>>(
        hn, nullptr, hn, sim, nullptr, nullptr, nullptr, Dh, Nv, 1);

    // top-k -> hash -> CSR2
    topk_k<<<Nv, 256>>>(sim, topi, topv);
    hash_ins_k<<<(Nv * Kp + 255) / 256, 256>>>(topi, topv, hkey, hsum, hcnt);
    hash_emit_k<<<HCAP / 256, 256>>>(hkey, hsum, hcnt, cooi, cooj, coow, nnz, deg2);
    scan2_k<<<1, 1024>>>(deg2, rpt2, fil2);
    fill2_k<<<(Nv * Kp + 255) / 256, 256>>>(cooi, cooj, coow, nnz, rpt2, fil2, col2, wcs2);

    // layer-1 propagates (both views), batched W2 GEMM, layer-2 propagates
    prop_k<Dh, 1><<<Nv, Dh>>>(xw1, rptr, csrc, dinv, b1, h1);
    spmm_csr_k<1><<<Nv, Dh>>>(rpt2, col2, wcs2, xw1, b1, g1);
    mma_nt_k<false, false><<<dim3(2, 32, 2), 256, SMEM_DYN>>>(
        h1, g1, w2t, bufB, bufB2, nullptr, nullptr, Dh, Dh, 0);
    prop_k<Dh, 2><<<Nv, Dh>>>(bufB, rptr, csrc, dinv, b2, z1);
    spmm_csr_k<2><<<Nv, Dh>>>(rpt2, col2, wcs2, bufB2, b2, z2);

    // fused z1n @ z2n^T: row exp-sums + diag
    mma_nt_k<true, false><<<dim3(32, 32, 1), 256, SMEM_DYN>>>(
        z1, nullptr, z2, nullptr, nullptr, gs, gd, Dh, Nv, 0);

    // pf/pb + loss (grid sized to true nnz upper bound Nv*Kp)
    pfpb_k<<<(Nv * Kp + 7) / 8, 256>>>(cooi, cooj, coow, nnz, z1, z2, gs, pf, pb);
    loss_k<<<1, 256>>>(gd, gs, pf, pb, out);
}